// round 7
// baseline (speedup 1.0000x reference)
#include <cuda_runtime.h>
#include <cuda_bf16.h>
#include <math.h>
#include <stdint.h>

#define N_TOK 4096
#define D_DIM 1024
#define E_NUM 8
#define I_DIM 1408
#define PAIRS (N_TOK * 2)
#define MT_MAX 64
#define AS2 40   // bf16 per smem row: 32 data + 8 pad (80B = 5x16B, ldsm conflict-free)

#define W_ELEMS ((size_t)E_NUM * I_DIM * D_DIM)

// ---------------- device scratch (static: allocation-guard safe) -------------
__device__ int   d_topk_idx[N_TOK * 2];
__device__ float d_topk_prob[N_TOK * 2];
__device__ int   d_counts[E_NUM];
__device__ int   d_offsets[E_NUM + 1];
__device__ int   d_cursor[E_NUM];
__device__ int   d_pair_token[PAIRS];
__device__ float d_pair_prob[PAIRS];
__device__ int   d_pair_pos[N_TOK * 2];
__device__ float d_Ypart[(size_t)PAIRS * D_DIM];

// split bf16 planes: [0]=hi, [1]=lo
__device__ __nv_bfloat16 s_x [2][(size_t)N_TOK * D_DIM];
__device__ __nv_bfloat16 s_wg[2][W_ELEMS];
__device__ __nv_bfloat16 s_wu[2][W_ELEMS];
__device__ __nv_bfloat16 s_wd[2][W_ELEMS];
__device__ __nv_bfloat16 s_H [2][(size_t)PAIRS * I_DIM];

// ---------------- PTX helpers ------------------------------------------------
__device__ __forceinline__ void cp16b(__nv_bfloat16* dst_smem, const __nv_bfloat16* src, bool pred) {
    uint32_t d = (uint32_t)__cvta_generic_to_shared(dst_smem);
    int sz = pred ? 16 : 0;
    asm volatile("cp.async.cg.shared.global [%0], [%1], 16, %2;\n"
                 :: "r"(d), "l"(src), "r"(sz));
}
__device__ __forceinline__ void cp_commit() {
    asm volatile("cp.async.commit_group;\n");
}
template <int N>
__device__ __forceinline__ void cp_wait() {
    asm volatile("cp.async.wait_group %0;\n" :: "n"(N));
}
__device__ __forceinline__ void mma_bf16(float c[4],
                                         uint32_t a0, uint32_t a1, uint32_t a2, uint32_t a3,
                                         uint32_t b0, uint32_t b1) {
    asm volatile(
        "mma.sync.aligned.m16n8k16.row.col.f32.bf16.bf16.f32 "
        "{%0,%1,%2,%3}, {%4,%5,%6,%7}, {%8,%9}, {%0,%1,%2,%3};\n"
        : "+f"(c[0]), "+f"(c[1]), "+f"(c[2]), "+f"(c[3])
        : "r"(a0), "r"(a1), "r"(a2), "r"(a3), "r"(b0), "r"(b1));
}
__device__ __forceinline__ void ldsm4(uint32_t& r0, uint32_t& r1, uint32_t& r2, uint32_t& r3,
                                      const __nv_bfloat16* p) {
    uint32_t a = (uint32_t)__cvta_generic_to_shared(p);
    asm volatile("ldmatrix.sync.aligned.m8n8.x4.shared.b16 {%0,%1,%2,%3}, [%4];\n"
                 : "=r"(r0), "=r"(r1), "=r"(r2), "=r"(r3) : "r"(a));
}

// ---------------- split: fp32 -> bf16 hi/lo planes ---------------------------
__global__ void split_kernel(const float4* __restrict__ src,
                             uint2* __restrict__ hi, uint2* __restrict__ lo, int n4) {
    int i = blockIdx.x * blockDim.x + threadIdx.x;
    if (i >= n4) return;
    float4 v = src[i];
    __nv_bfloat16 h0 = __float2bfloat16_rn(v.x);
    __nv_bfloat16 h1 = __float2bfloat16_rn(v.y);
    __nv_bfloat16 h2 = __float2bfloat16_rn(v.z);
    __nv_bfloat16 h3 = __float2bfloat16_rn(v.w);
    __nv_bfloat16 l0 = __float2bfloat16_rn(v.x - __bfloat162float(h0));
    __nv_bfloat16 l1 = __float2bfloat16_rn(v.y - __bfloat162float(h1));
    __nv_bfloat16 l2 = __float2bfloat16_rn(v.z - __bfloat162float(h2));
    __nv_bfloat16 l3 = __float2bfloat16_rn(v.w - __bfloat162float(h3));
    __nv_bfloat162 hA = __halves2bfloat162(h0, h1), hB = __halves2bfloat162(h2, h3);
    __nv_bfloat162 lA = __halves2bfloat162(l0, l1), lB = __halves2bfloat162(l2, l3);
    uint2 ho, loo;
    ho.x  = *(uint32_t*)&hA;  ho.y  = *(uint32_t*)&hB;
    loo.x = *(uint32_t*)&lA;  loo.y = *(uint32_t*)&lB;
    hi[i] = ho;
    lo[i] = loo;
}

// fused 3-matrix weight split: blockIdx.y selects {wg, wu, wd}
__global__ void wsplit_kernel(const float4* __restrict__ wg,
                              const float4* __restrict__ wu,
                              const float4* __restrict__ wd,
                              uint2* __restrict__ g_hi, uint2* __restrict__ g_lo,
                              uint2* __restrict__ u_hi, uint2* __restrict__ u_lo,
                              uint2* __restrict__ d_hi, uint2* __restrict__ d_lo,
                              int n4) {
    int i = blockIdx.x * blockDim.x + threadIdx.x;
    if (i >= n4) return;
    const float4* src;
    uint2 *hi, *lo;
    if (blockIdx.y == 0)      { src = wg; hi = g_hi; lo = g_lo; }
    else if (blockIdx.y == 1) { src = wu; hi = u_hi; lo = u_lo; }
    else                      { src = wd; hi = d_hi; lo = d_lo; }
    float4 v = src[i];
    __nv_bfloat16 h0 = __float2bfloat16_rn(v.x);
    __nv_bfloat16 h1 = __float2bfloat16_rn(v.y);
    __nv_bfloat16 h2 = __float2bfloat16_rn(v.z);
    __nv_bfloat16 h3 = __float2bfloat16_rn(v.w);
    __nv_bfloat16 l0 = __float2bfloat16_rn(v.x - __bfloat162float(h0));
    __nv_bfloat16 l1 = __float2bfloat16_rn(v.y - __bfloat162float(h1));
    __nv_bfloat16 l2 = __float2bfloat16_rn(v.z - __bfloat162float(h2));
    __nv_bfloat16 l3 = __float2bfloat16_rn(v.w - __bfloat162float(h3));
    __nv_bfloat162 hA = __halves2bfloat162(h0, h1), hB = __halves2bfloat162(h2, h3);
    __nv_bfloat162 lA = __halves2bfloat162(l0, l1), lB = __halves2bfloat162(l2, l3);
    uint2 ho, loo;
    ho.x  = *(uint32_t*)&hA;  ho.y  = *(uint32_t*)&hB;
    loo.x = *(uint32_t*)&lA;  loo.y = *(uint32_t*)&lB;
    hi[i] = ho;
    lo[i] = loo;
}

// ---------------- init / router / scan / scatter ------------------------------
__global__ void init_kernel() {
    if (threadIdx.x < E_NUM) d_counts[threadIdx.x] = 0;
}

__global__ void router_kernel(const float* __restrict__ x,
                              const float* __restrict__ gw) {
    __shared__ float xs[D_DIM];
    __shared__ float sc[E_NUM];
    int t = blockIdx.x;
    const float* xp = x + (size_t)t * D_DIM;
    for (int i = threadIdx.x; i < D_DIM; i += blockDim.x) xs[i] = xp[i];
    __syncthreads();
    int w = threadIdx.x >> 5, lane = threadIdx.x & 31;
    float s = 0.f;
    const float* g = gw + (size_t)w * D_DIM;
    for (int j = lane; j < D_DIM; j += 32) s += xs[j] * g[j];
    #pragma unroll
    for (int o = 16; o; o >>= 1) s += __shfl_xor_sync(0xffffffffu, s, o);
    if (lane == 0) sc[w] = s;
    __syncthreads();
    if (threadIdx.x == 0) {
        int i0 = 0; float s0 = sc[0];
        #pragma unroll
        for (int e = 1; e < E_NUM; e++) if (sc[e] > s0) { s0 = sc[e]; i0 = e; }
        int i1 = -1; float s1 = -1e30f;
        #pragma unroll
        for (int e = 0; e < E_NUM; e++)
            if (e != i0 && sc[e] > s1) { s1 = sc[e]; i1 = e; }
        float z  = expf(s1 - s0);
        float p0 = 1.f / (1.f + z);
        float p1 = z * p0;
        d_topk_idx[t * 2]     = i0;  d_topk_idx[t * 2 + 1]  = i1;
        d_topk_prob[t * 2]    = p0;  d_topk_prob[t * 2 + 1] = p1;
        atomicAdd(&d_counts[i0], 1);
        atomicAdd(&d_counts[i1], 1);
    }
}

__global__ void scan_kernel() {
    int off = 0;
    #pragma unroll
    for (int e = 0; e < E_NUM; e++) {
        d_offsets[e] = off;
        d_cursor[e]  = off;
        off += d_counts[e];
    }
    d_offsets[E_NUM] = off;
}

__global__ void scatter_kernel() {
    int t = blockIdx.x * blockDim.x + threadIdx.x;
    if (t >= N_TOK) return;
    #pragma unroll
    for (int k = 0; k < 2; k++) {
        int e = d_topk_idx[t * 2 + k];
        int pos = atomicAdd(&d_cursor[e], 1);
        d_pair_token[pos]     = t;
        d_pair_prob[pos]      = d_topk_prob[t * 2 + k];
        d_pair_pos[t * 2 + k] = pos;
    }
}

// =============================================================================
// gemm1: 3-stage single-sync pipeline, term-major mma, ldmatrix, K=32/stage
// Block 128(M) x 64(N), 256 threads, warp tile 64x16.
// =============================================================================
struct Smem1 {
    __nv_bfloat16 Ah[3][128 * AS2], Al[3][128 * AS2];
    __nv_bfloat16 Bgh[3][64 * AS2], Bgl[3][64 * AS2];
    __nv_bfloat16 Buh[3][64 * AS2], Bul[3][64 * AS2];
    int rowtok[128];
};

__global__ __launch_bounds__(256) void gemm1_kernel() {
    extern __shared__ char smem_raw[];
    Smem1& S = *reinterpret_cast<Smem1*>(smem_raw);

    int e  = blockIdx.y >> 6;
    int mt = blockIdx.y & (MT_MAX - 1);
    int cnt = d_counts[e];
    int m0  = mt * 128;
    if (m0 >= cnt) return;
    int n0   = blockIdx.x * 64;
    int base = d_offsets[e];

    int tid = threadIdx.x;
    if (tid < 128) {
        int r = m0 + tid;
        S.rowtok[tid] = (r < cnt) ? d_pair_token[base + r] : -1;
    }
    __syncthreads();

    int ld_row = tid >> 2;           // 0..63
    int ld_c   = (tid & 3) * 8;
    int tokA0 = S.rowtok[ld_row];
    int tokA1 = S.rowtok[ld_row + 64];
    const __nv_bfloat16* gx0h = s_x[0] + (size_t)(tokA0 < 0 ? 0 : tokA0) * D_DIM + ld_c;
    const __nv_bfloat16* gx0l = s_x[1] + (size_t)(tokA0 < 0 ? 0 : tokA0) * D_DIM + ld_c;
    const __nv_bfloat16* gx1h = s_x[0] + (size_t)(tokA1 < 0 ? 0 : tokA1) * D_DIM + ld_c;
    const __nv_bfloat16* gx1l = s_x[1] + (size_t)(tokA1 < 0 ? 0 : tokA1) * D_DIM + ld_c;
    bool ap0 = tokA0 >= 0, ap1 = tokA1 >= 0;

    size_t wE = (size_t)e * I_DIM * D_DIM;
    size_t bro = wE + (size_t)(n0 + ld_row) * D_DIM + ld_c;
    const __nv_bfloat16* gbgh = s_wg[0] + bro;
    const __nv_bfloat16* gbgl = s_wg[1] + bro;
    const __nv_bfloat16* gbuh = s_wu[0] + bro;
    const __nv_bfloat16* gbul = s_wu[1] + bro;

    int wid = tid >> 5, lane = tid & 31;
    int wm0 = (wid >> 2) * 64, wn0 = (wid & 3) * 16;
    int a_loff = ((lane & 7) + ((lane >> 3) & 1) * 8) * AS2 + ((lane >> 4) & 1) * 8;
    int b_loff = ((lane & 7) + ((lane >> 4) & 1) * 8) * AS2 + ((lane >> 3) & 1) * 8;
    int g  = lane >> 2, tg = lane & 3;

    float accG[4][2][4], accU[4][2][4];
    #pragma unroll
    for (int i = 0; i < 4; i++)
        #pragma unroll
        for (int j = 0; j < 2; j++)
            #pragma unroll
            for (int k = 0; k < 4; k++) { accG[i][j][k] = 0.f; accU[i][j][k] = 0.f; }

    const int TS = D_DIM / 32;   // 32 stages
    int ld_dst = ld_row * AS2 + ld_c;

    auto load_stage = [&](int buf, int k0) {
        cp16b(&S.Ah[buf][ld_dst], gx0h + k0, ap0);
        cp16b(&S.Al[buf][ld_dst], gx0l + k0, ap0);
        cp16b(&S.Ah[buf][ld_dst + 64 * AS2], gx1h + k0, ap1);
        cp16b(&S.Al[buf][ld_dst + 64 * AS2], gx1l + k0, ap1);
        cp16b(&S.Bgh[buf][ld_dst], gbgh + k0, true);
        cp16b(&S.Bgl[buf][ld_dst], gbgl + k0, true);
        cp16b(&S.Buh[buf][ld_dst], gbuh + k0, true);
        cp16b(&S.Bul[buf][ld_dst], gbul + k0, true);
        cp_commit();
    };

    load_stage(0, 0);
    load_stage(1, 32);

    int buf = 0;
    for (int t = 0; t < TS; t++) {
        if (t + 1 < TS) cp_wait<1>(); else cp_wait<0>();
        __syncthreads();
        if (t + 2 < TS) {
            int nb = buf + 2; if (nb >= 3) nb -= 3;
            load_stage(nb, (t + 2) * 32);
        }

        const __nv_bfloat16* ah  = S.Ah[buf];
        const __nv_bfloat16* al  = S.Al[buf];
        const __nv_bfloat16* bgh = S.Bgh[buf];
        const __nv_bfloat16* bgl = S.Bgl[buf];
        const __nv_bfloat16* buh = S.Buh[buf];
        const __nv_bfloat16* bul = S.Bul[buf];

        #pragma unroll
        for (int sub = 0; sub < 2; sub++) {
            int ko = sub * 16;
            uint32_t afh[4][4], afl[4][4];
            #pragma unroll
            for (int mi = 0; mi < 4; mi++) {
                int ro = (wm0 + mi * 16) * AS2 + ko + a_loff;
                ldsm4(afh[mi][0], afh[mi][1], afh[mi][2], afh[mi][3], &ah[ro]);
                ldsm4(afl[mi][0], afl[mi][1], afl[mi][2], afl[mi][3], &al[ro]);
            }
            int bo = wn0 * AS2 + ko + b_loff;
            uint32_t gh[4], gl[4], uh[4], ul[4];
            ldsm4(gh[0], gh[1], gh[2], gh[3], &bgh[bo]);
            ldsm4(gl[0], gl[1], gl[2], gl[3], &bgl[bo]);
            ldsm4(uh[0], uh[1], uh[2], uh[3], &buh[bo]);
            ldsm4(ul[0], ul[1], ul[2], ul[3], &bul[bo]);
            // term-major: hi*hi (G,U), then hi*lo, then lo*hi — breaks RAW chains
            #pragma unroll
            for (int ni = 0; ni < 2; ni++)
                #pragma unroll
                for (int mi = 0; mi < 4; mi++) {
                    mma_bf16(accG[mi][ni], afh[mi][0], afh[mi][1], afh[mi][2], afh[mi][3], gh[ni*2], gh[ni*2+1]);
                    mma_bf16(accU[mi][ni], afh[mi][0], afh[mi][1], afh[mi][2], afh[mi][3], uh[ni*2], uh[ni*2+1]);
                }
            #pragma unroll
            for (int ni = 0; ni < 2; ni++)
                #pragma unroll
                for (int mi = 0; mi < 4; mi++) {
                    mma_bf16(accG[mi][ni], afh[mi][0], afh[mi][1], afh[mi][2], afh[mi][3], gl[ni*2], gl[ni*2+1]);
                    mma_bf16(accU[mi][ni], afh[mi][0], afh[mi][1], afh[mi][2], afh[mi][3], ul[ni*2], ul[ni*2+1]);
                }
            #pragma unroll
            for (int ni = 0; ni < 2; ni++)
                #pragma unroll
                for (int mi = 0; mi < 4; mi++) {
                    mma_bf16(accG[mi][ni], afl[mi][0], afl[mi][1], afl[mi][2], afl[mi][3], gh[ni*2], gh[ni*2+1]);
                    mma_bf16(accU[mi][ni], afl[mi][0], afl[mi][1], afl[mi][2], afl[mi][3], uh[ni*2], uh[ni*2+1]);
                }
        }
        buf++; if (buf == 3) buf = 0;
    }

    // epilogue
    #pragma unroll
    for (int mi = 0; mi < 4; mi++) {
        #pragma unroll
        for (int ni = 0; ni < 2; ni++) {
            int col = n0 + wn0 + ni * 8 + tg * 2;
            #pragma unroll
            for (int half = 0; half < 2; half++) {
                int r = m0 + wm0 + mi * 16 + g + half * 8;
                if (r < cnt) {
                    size_t out = (size_t)(base + r) * I_DIM + col;
                    float gv0 = accG[mi][ni][half * 2];
                    float gv1 = accG[mi][ni][half * 2 + 1];
                    float h0 = gv0 / (1.f + expf(-gv0)) * accU[mi][ni][half * 2];
                    float h1 = gv1 / (1.f + expf(-gv1)) * accU[mi][ni][half * 2 + 1];
                    __nv_bfloat16 H0 = __float2bfloat16_rn(h0);
                    __nv_bfloat16 H1 = __float2bfloat16_rn(h1);
                    __nv_bfloat16 L0 = __float2bfloat16_rn(h0 - __bfloat162float(H0));
                    __nv_bfloat16 L1 = __float2bfloat16_rn(h1 - __bfloat162float(H1));
                    *(__nv_bfloat162*)&s_H[0][out] = __halves2bfloat162(H0, H1);
                    *(__nv_bfloat162*)&s_H[1][out] = __halves2bfloat162(L0, L1);
                }
            }
        }
    }
}

// =============================================================================
// gemm2: 3-stage single-sync pipeline, term-major mma, ldmatrix, K=32/stage
// Block 128(M) x 128(N), 256 threads, warp tile 64x32.
// =============================================================================
struct Smem2 {
    __nv_bfloat16 Ah[3][128 * AS2], Al[3][128 * AS2];
    __nv_bfloat16 Bh[3][128 * AS2], Bl[3][128 * AS2];
    float rowprob[128];
};

__global__ __launch_bounds__(256) void gemm2_kernel() {
    extern __shared__ char smem_raw[];
    Smem2& S = *reinterpret_cast<Smem2*>(smem_raw);

    int e  = blockIdx.y >> 6;
    int mt = blockIdx.y & (MT_MAX - 1);
    int cnt = d_counts[e];
    int m0  = mt * 128;
    if (m0 >= cnt) return;
    int n0   = blockIdx.x * 128;
    int base = d_offsets[e];

    int tid = threadIdx.x;
    if (tid < 128) {
        int r = m0 + tid;
        S.rowprob[tid] = (r < cnt) ? d_pair_prob[base + r] : 0.f;
    }
    __syncthreads();

    int ld_row = tid >> 2;
    int ld_c   = (tid & 3) * 8;
    bool av0 = (m0 + ld_row) < cnt;
    bool av1 = (m0 + ld_row + 64) < cnt;
    size_t ar0 = (size_t)(base + (av0 ? m0 + ld_row : 0)) * I_DIM + ld_c;
    size_t ar1 = (size_t)(base + (av1 ? m0 + ld_row + 64 : 0)) * I_DIM + ld_c;
    const __nv_bfloat16* ga0h = s_H[0] + ar0;
    const __nv_bfloat16* ga0l = s_H[1] + ar0;
    const __nv_bfloat16* ga1h = s_H[0] + ar1;
    const __nv_bfloat16* ga1l = s_H[1] + ar1;

    size_t wE = (size_t)e * D_DIM * I_DIM;
    size_t br0 = wE + (size_t)(n0 + ld_row) * I_DIM + ld_c;
    size_t br1 = wE + (size_t)(n0 + ld_row + 64) * I_DIM + ld_c;
    const __nv_bfloat16* gb0h = s_wd[0] + br0;
    const __nv_bfloat16* gb0l = s_wd[1] + br0;
    const __nv_bfloat16* gb1h = s_wd[0] + br1;
    const __nv_bfloat16* gb1l = s_wd[1] + br1;

    int wid = tid >> 5, lane = tid & 31;
    int wm0 = (wid >> 2) * 64, wn0 = (wid & 3) * 32;
    int a_loff = ((lane & 7) + ((lane >> 3) & 1) * 8) * AS2 + ((lane >> 4) & 1) * 8;
    int b_loff = ((lane & 7) + ((lane >> 4) & 1) * 8) * AS2 + ((lane >> 3) & 1) * 8;
    int g  = lane >> 2, tg = lane & 3;

    float acc[4][4][4];
    #pragma unroll
    for (int i = 0; i < 4; i++)
        #pragma unroll
        for (int j = 0; j < 4; j++)
            #pragma unroll
            for (int k = 0; k < 4; k++) acc[i][j][k] = 0.f;

    const int TS = I_DIM / 32;   // 44 stages
    int ld_dst = ld_row * AS2 + ld_c;

    auto load_stage = [&](int buf, int k0) {
        cp16b(&S.Ah[buf][ld_dst], ga0h + k0, av0);
        cp16b(&S.Al[buf][ld_dst], ga0l + k0, av0);
        cp16b(&S.Ah[buf][ld_dst + 64 * AS2], ga1h + k0, av1);
        cp16b(&S.Al[buf][ld_dst + 64 * AS2], ga1l + k0, av1);
        cp16b(&S.Bh[buf][ld_dst], gb0h + k0, true);
        cp16b(&S.Bl[buf][ld_dst], gb0l + k0, true);
        cp16b(&S.Bh[buf][ld_dst + 64 * AS2], gb1h + k0, true);
        cp16b(&S.Bl[buf][ld_dst + 64 * AS2], gb1l + k0, true);
        cp_commit();
    };

    load_stage(0, 0);
    load_stage(1, 32);

    int buf = 0;
    for (int t = 0; t < TS; t++) {
        if (t + 1 < TS) cp_wait<1>(); else cp_wait<0>();
        __syncthreads();
        if (t + 2 < TS) {
            int nb = buf + 2; if (nb >= 3) nb -= 3;
            load_stage(nb, (t + 2) * 32);
        }

        const __nv_bfloat16* ah = S.Ah[buf];
        const __nv_bfloat16* al = S.Al[buf];
        const __nv_bfloat16* bh = S.Bh[buf];
        const __nv_bfloat16* bl = S.Bl[buf];

        #pragma unroll
        for (int sub = 0; sub < 2; sub++) {
            int ko = sub * 16;
            uint32_t afh[4][4], afl[4][4];
            #pragma unroll
            for (int mi = 0; mi < 4; mi++) {
                int ro = (wm0 + mi * 16) * AS2 + ko + a_loff;
                ldsm4(afh[mi][0], afh[mi][1], afh[mi][2], afh[mi][3], &ah[ro]);
                ldsm4(afl[mi][0], afl[mi][1], afl[mi][2], afl[mi][3], &al[ro]);
            }
            uint32_t bhr[2][4], blr[2][4];
            #pragma unroll
            for (int half = 0; half < 2; half++) {
                int bo = (wn0 + half * 16) * AS2 + ko + b_loff;
                ldsm4(bhr[half][0], bhr[half][1], bhr[half][2], bhr[half][3], &bh[bo]);
                ldsm4(blr[half][0], blr[half][1], blr[half][2], blr[half][3], &bl[bo]);
            }
            // term-major ordering
            #pragma unroll
            for (int ni = 0; ni < 4; ni++) {
                uint32_t b0 = bhr[ni >> 1][(ni & 1) * 2], b1 = bhr[ni >> 1][(ni & 1) * 2 + 1];
                #pragma unroll
                for (int mi = 0; mi < 4; mi++)
                    mma_bf16(acc[mi][ni], afh[mi][0], afh[mi][1], afh[mi][2], afh[mi][3], b0, b1);
            }
            #pragma unroll
            for (int ni = 0; ni < 4; ni++) {
                uint32_t b0 = blr[ni >> 1][(ni & 1) * 2], b1 = blr[ni >> 1][(ni & 1) * 2 + 1];
                #pragma unroll
                for (int mi = 0; mi < 4; mi++)
                    mma_bf16(acc[mi][ni], afh[mi][0], afh[mi][1], afh[mi][2], afh[mi][3], b0, b1);
            }
            #pragma unroll
            for (int ni = 0; ni < 4; ni++) {
                uint32_t b0 = bhr[ni >> 1][(ni & 1) * 2], b1 = bhr[ni >> 1][(ni & 1) * 2 + 1];
                #pragma unroll
                for (int mi = 0; mi < 4; mi++)
                    mma_bf16(acc[mi][ni], afl[mi][0], afl[mi][1], afl[mi][2], afl[mi][3], b0, b1);
            }
        }
        buf++; if (buf == 3) buf = 0;
    }

    // epilogue
    #pragma unroll
    for (int mi = 0; mi < 4; mi++) {
        #pragma unroll
        for (int half = 0; half < 2; half++) {
            int rb = wm0 + mi * 16 + g + half * 8;
            int r  = m0 + rb;
            if (r >= cnt) continue;
            float p = S.rowprob[rb];
            size_t out = (size_t)(base + r) * D_DIM + n0 + wn0;
            #pragma unroll
            for (int ni = 0; ni < 4; ni++) {
                int col = ni * 8 + tg * 2;
                d_Ypart[out + col]     = p * acc[mi][ni][half * 2];
                d_Ypart[out + col + 1] = p * acc[mi][ni][half * 2 + 1];
            }
        }
    }
}

// ---------------- combine ----------------------------------------------------
__global__ void combine_kernel(float* __restrict__ y) {
    int i = blockIdx.x * blockDim.x + threadIdx.x;
    int t = i / (D_DIM / 4);
    int c = (i % (D_DIM / 4)) * 4;
    int p0 = d_pair_pos[t * 2];
    int p1 = d_pair_pos[t * 2 + 1];
    float4 a = *(const float4*)&d_Ypart[(size_t)p0 * D_DIM + c];
    float4 b = *(const float4*)&d_Ypart[(size_t)p1 * D_DIM + c];
    float4 o = make_float4(a.x + b.x, a.y + b.y, a.z + b.z, a.w + b.w);
    *(float4*)&y[(size_t)t * D_DIM + c] = o;
}

// ---------------- launch -----------------------------------------------------
extern "C" void kernel_launch(void* const* d_in, const int* in_sizes, int n_in,
                              void* d_out, int out_size) {
    const float* x  = (const float*)d_in[0];
    const float* gw = (const float*)d_in[1];
    const float* wg = (const float*)d_in[2];
    const float* wu = (const float*)d_in[3];
    const float* wd = (const float*)d_in[4];
    float* y = (float*)d_out;

    cudaFuncSetAttribute(gemm1_kernel, cudaFuncAttributeMaxDynamicSharedMemorySize, sizeof(Smem1));
    cudaFuncSetAttribute(gemm2_kernel, cudaFuncAttributeMaxDynamicSharedMemorySize, sizeof(Smem2));

    __nv_bfloat16 *p_x, *p_wg, *p_wu, *p_wd;
    cudaGetSymbolAddress((void**)&p_x,  s_x);
    cudaGetSymbolAddress((void**)&p_wg, s_wg);
    cudaGetSymbolAddress((void**)&p_wu, s_wu);
    cudaGetSymbolAddress((void**)&p_wd, s_wd);
    size_t xN = (size_t)N_TOK * D_DIM;

    init_kernel<<<1, 32>>>();
    router_kernel<<<N_TOK, 256>>>(x, gw);

    {   // splits
        int n4 = (int)(xN / 4);
        split_kernel<<<(n4 + 255) / 256, 256>>>((const float4*)x, (uint2*)p_x, (uint2*)(p_x + xN), n4);
        int w4 = (int)(W_ELEMS / 4);
        wsplit_kernel<<<dim3((w4 + 255) / 256, 3), 256>>>(
            (const float4*)wg, (const float4*)wu, (const float4*)wd,
            (uint2*)p_wg, (uint2*)(p_wg + W_ELEMS),
            (uint2*)p_wu, (uint2*)(p_wu + W_ELEMS),
            (uint2*)p_wd, (uint2*)(p_wd + W_ELEMS), w4);
    }

    scan_kernel<<<1, 1>>>();
    scatter_kernel<<<(N_TOK + 255) / 256, 256>>>();
    gemm1_kernel<<<dim3(I_DIM / 64, E_NUM * MT_MAX), 256, sizeof(Smem1)>>>();
    gemm2_kernel<<<dim3(D_DIM / 128, E_NUM * MT_MAX), 256, sizeof(Smem2)>>>();
    combine_kernel<<<(N_TOK * D_DIM / 4 + 255) / 256, 256>>>(y);
}

// round 8
// speedup vs baseline: 1.2183x; 1.2183x over previous
#include <cuda_runtime.h>
#include <cuda_bf16.h>
#include <math.h>
#include <stdint.h>

#define N_TOK 4096
#define D_DIM 1024
#define E_NUM 8
#define I_DIM 1408
#define PAIRS (N_TOK * 2)
#define MT_MAX 64
#define AS2 40   // bf16 per smem row: 32 data + 8 pad (80B = 5x16B, ldsm conflict-free)

#define W_ELEMS ((size_t)E_NUM * I_DIM * D_DIM)

// ---------------- device scratch (static: allocation-guard safe) -------------
__device__ int   d_topk_idx[N_TOK * 2];
__device__ float d_topk_prob[N_TOK * 2];
__device__ int   d_counts[E_NUM];
__device__ int   d_offsets[E_NUM + 1];
__device__ int   d_cursor[E_NUM];
__device__ int   d_pair_token[PAIRS];
__device__ float d_pair_prob[PAIRS];

// split bf16 planes: [0]=hi, [1]=lo
__device__ __nv_bfloat16 s_x [2][(size_t)N_TOK * D_DIM];
__device__ __nv_bfloat16 s_wg[2][W_ELEMS];
__device__ __nv_bfloat16 s_wu[2][W_ELEMS];
__device__ __nv_bfloat16 s_wd[2][W_ELEMS];
__device__ __nv_bfloat16 s_H [2][(size_t)PAIRS * I_DIM];

// ---------------- PTX helpers ------------------------------------------------
__device__ __forceinline__ void cp16b(__nv_bfloat16* dst_smem, const __nv_bfloat16* src, bool pred) {
    uint32_t d = (uint32_t)__cvta_generic_to_shared(dst_smem);
    int sz = pred ? 16 : 0;
    asm volatile("cp.async.cg.shared.global [%0], [%1], 16, %2;\n"
                 :: "r"(d), "l"(src), "r"(sz));
}
__device__ __forceinline__ void cp_commit() {
    asm volatile("cp.async.commit_group;\n");
}
template <int N>
__device__ __forceinline__ void cp_wait() {
    asm volatile("cp.async.wait_group %0;\n" :: "n"(N));
}
__device__ __forceinline__ void mma_bf16(float c[4],
                                         uint32_t a0, uint32_t a1, uint32_t a2, uint32_t a3,
                                         uint32_t b0, uint32_t b1) {
    asm volatile(
        "mma.sync.aligned.m16n8k16.row.col.f32.bf16.bf16.f32 "
        "{%0,%1,%2,%3}, {%4,%5,%6,%7}, {%8,%9}, {%0,%1,%2,%3};\n"
        : "+f"(c[0]), "+f"(c[1]), "+f"(c[2]), "+f"(c[3])
        : "r"(a0), "r"(a1), "r"(a2), "r"(a3), "r"(b0), "r"(b1));
}
__device__ __forceinline__ void ldsm4(uint32_t& r0, uint32_t& r1, uint32_t& r2, uint32_t& r3,
                                      const __nv_bfloat16* p) {
    uint32_t a = (uint32_t)__cvta_generic_to_shared(p);
    asm volatile("ldmatrix.sync.aligned.m8n8.x4.shared.b16 {%0,%1,%2,%3}, [%4];\n"
                 : "=r"(r0), "=r"(r1), "=r"(r2), "=r"(r3) : "r"(a));
}

// ---------------- split: fp32 -> bf16 hi/lo planes ---------------------------
__global__ void split_kernel(const float4* __restrict__ src,
                             uint2* __restrict__ hi, uint2* __restrict__ lo, int n4) {
    int i = blockIdx.x * blockDim.x + threadIdx.x;
    if (i >= n4) return;
    float4 v = src[i];
    __nv_bfloat16 h0 = __float2bfloat16_rn(v.x);
    __nv_bfloat16 h1 = __float2bfloat16_rn(v.y);
    __nv_bfloat16 h2 = __float2bfloat16_rn(v.z);
    __nv_bfloat16 h3 = __float2bfloat16_rn(v.w);
    __nv_bfloat16 l0 = __float2bfloat16_rn(v.x - __bfloat162float(h0));
    __nv_bfloat16 l1 = __float2bfloat16_rn(v.y - __bfloat162float(h1));
    __nv_bfloat16 l2 = __float2bfloat16_rn(v.z - __bfloat162float(h2));
    __nv_bfloat16 l3 = __float2bfloat16_rn(v.w - __bfloat162float(h3));
    __nv_bfloat162 hA = __halves2bfloat162(h0, h1), hB = __halves2bfloat162(h2, h3);
    __nv_bfloat162 lA = __halves2bfloat162(l0, l1), lB = __halves2bfloat162(l2, l3);
    uint2 ho, loo;
    ho.x  = *(uint32_t*)&hA;  ho.y  = *(uint32_t*)&hB;
    loo.x = *(uint32_t*)&lA;  loo.y = *(uint32_t*)&lB;
    hi[i] = ho;
    lo[i] = loo;
}

// fused 3-matrix weight split: blockIdx.y selects {wg, wu, wd}
__global__ void wsplit_kernel(const float4* __restrict__ wg,
                              const float4* __restrict__ wu,
                              const float4* __restrict__ wd,
                              uint2* __restrict__ g_hi, uint2* __restrict__ g_lo,
                              uint2* __restrict__ u_hi, uint2* __restrict__ u_lo,
                              uint2* __restrict__ d_hi, uint2* __restrict__ d_lo,
                              int n4) {
    int i = blockIdx.x * blockDim.x + threadIdx.x;
    if (i >= n4) return;
    const float4* src;
    uint2 *hi, *lo;
    if (blockIdx.y == 0)      { src = wg; hi = g_hi; lo = g_lo; }
    else if (blockIdx.y == 1) { src = wu; hi = u_hi; lo = u_lo; }
    else                      { src = wd; hi = d_hi; lo = d_lo; }
    float4 v = src[i];
    __nv_bfloat16 h0 = __float2bfloat16_rn(v.x);
    __nv_bfloat16 h1 = __float2bfloat16_rn(v.y);
    __nv_bfloat16 h2 = __float2bfloat16_rn(v.z);
    __nv_bfloat16 h3 = __float2bfloat16_rn(v.w);
    __nv_bfloat16 l0 = __float2bfloat16_rn(v.x - __bfloat162float(h0));
    __nv_bfloat16 l1 = __float2bfloat16_rn(v.y - __bfloat162float(h1));
    __nv_bfloat16 l2 = __float2bfloat16_rn(v.z - __bfloat162float(h2));
    __nv_bfloat16 l3 = __float2bfloat16_rn(v.w - __bfloat162float(h3));
    __nv_bfloat162 hA = __halves2bfloat162(h0, h1), hB = __halves2bfloat162(h2, h3);
    __nv_bfloat162 lA = __halves2bfloat162(l0, l1), lB = __halves2bfloat162(l2, l3);
    uint2 ho, loo;
    ho.x  = *(uint32_t*)&hA;  ho.y  = *(uint32_t*)&hB;
    loo.x = *(uint32_t*)&lA;  loo.y = *(uint32_t*)&lB;
    hi[i] = ho;
    lo[i] = loo;
}

// ---------------- init / router / scan / scatter / zero ----------------------
__global__ void init_kernel() {
    if (threadIdx.x < E_NUM) d_counts[threadIdx.x] = 0;
}

__global__ void zero_y_kernel(float4* __restrict__ y, int n4) {
    int i = blockIdx.x * blockDim.x + threadIdx.x;
    if (i < n4) y[i] = make_float4(0.f, 0.f, 0.f, 0.f);
}

__global__ void router_kernel(const float* __restrict__ x,
                              const float* __restrict__ gw) {
    __shared__ float xs[D_DIM];
    __shared__ float sc[E_NUM];
    int t = blockIdx.x;
    const float* xp = x + (size_t)t * D_DIM;
    for (int i = threadIdx.x; i < D_DIM; i += blockDim.x) xs[i] = xp[i];
    __syncthreads();
    int w = threadIdx.x >> 5, lane = threadIdx.x & 31;
    float s = 0.f;
    const float* g = gw + (size_t)w * D_DIM;
    for (int j = lane; j < D_DIM; j += 32) s += xs[j] * g[j];
    #pragma unroll
    for (int o = 16; o; o >>= 1) s += __shfl_xor_sync(0xffffffffu, s, o);
    if (lane == 0) sc[w] = s;
    __syncthreads();
    if (threadIdx.x == 0) {
        int i0 = 0; float s0 = sc[0];
        #pragma unroll
        for (int e = 1; e < E_NUM; e++) if (sc[e] > s0) { s0 = sc[e]; i0 = e; }
        int i1 = -1; float s1 = -1e30f;
        #pragma unroll
        for (int e = 0; e < E_NUM; e++)
            if (e != i0 && sc[e] > s1) { s1 = sc[e]; i1 = e; }
        float z  = expf(s1 - s0);
        float p0 = 1.f / (1.f + z);
        float p1 = z * p0;
        d_topk_idx[t * 2]     = i0;  d_topk_idx[t * 2 + 1]  = i1;
        d_topk_prob[t * 2]    = p0;  d_topk_prob[t * 2 + 1] = p1;
        atomicAdd(&d_counts[i0], 1);
        atomicAdd(&d_counts[i1], 1);
    }
}

__global__ void scan_kernel() {
    int off = 0;
    #pragma unroll
    for (int e = 0; e < E_NUM; e++) {
        d_offsets[e] = off;
        d_cursor[e]  = off;
        off += d_counts[e];
    }
    d_offsets[E_NUM] = off;
}

__global__ void scatter_kernel() {
    int t = blockIdx.x * blockDim.x + threadIdx.x;
    if (t >= N_TOK) return;
    #pragma unroll
    for (int k = 0; k < 2; k++) {
        int e = d_topk_idx[t * 2 + k];
        int pos = atomicAdd(&d_cursor[e], 1);
        d_pair_token[pos] = t;
        d_pair_prob[pos]  = d_topk_prob[t * 2 + k];
    }
}

// =============================================================================
// gemm1: R5 structure (2-stage, ldmatrix, K=32/stage), 2 CTAs/SM forced.
// Block 128(M) x 64(N), 256 threads, warp tile 64x16.
// =============================================================================
struct Smem1 {
    __nv_bfloat16 Ah[2][128 * AS2], Al[2][128 * AS2];
    __nv_bfloat16 Bgh[2][64 * AS2], Bgl[2][64 * AS2];
    __nv_bfloat16 Buh[2][64 * AS2], Bul[2][64 * AS2];
    int rowtok[128];
};

__global__ __launch_bounds__(256, 2) void gemm1_kernel() {
    extern __shared__ char smem_raw[];
    Smem1& S = *reinterpret_cast<Smem1*>(smem_raw);

    int e  = blockIdx.y >> 6;
    int mt = blockIdx.y & (MT_MAX - 1);
    int cnt = d_counts[e];
    int m0  = mt * 128;
    if (m0 >= cnt) return;
    int n0   = blockIdx.x * 64;
    int base = d_offsets[e];

    int tid = threadIdx.x;
    if (tid < 128) {
        int r = m0 + tid;
        S.rowtok[tid] = (r < cnt) ? d_pair_token[base + r] : -1;
    }
    __syncthreads();

    int ld_row = tid >> 2;           // 0..63
    int ld_c   = (tid & 3) * 8;
    int tokA0 = S.rowtok[ld_row];
    int tokA1 = S.rowtok[ld_row + 64];
    const __nv_bfloat16* gx0h = s_x[0] + (size_t)(tokA0 < 0 ? 0 : tokA0) * D_DIM + ld_c;
    const __nv_bfloat16* gx0l = s_x[1] + (size_t)(tokA0 < 0 ? 0 : tokA0) * D_DIM + ld_c;
    const __nv_bfloat16* gx1h = s_x[0] + (size_t)(tokA1 < 0 ? 0 : tokA1) * D_DIM + ld_c;
    const __nv_bfloat16* gx1l = s_x[1] + (size_t)(tokA1 < 0 ? 0 : tokA1) * D_DIM + ld_c;
    bool ap0 = tokA0 >= 0, ap1 = tokA1 >= 0;

    size_t wE = (size_t)e * I_DIM * D_DIM;
    size_t bro = wE + (size_t)(n0 + ld_row) * D_DIM + ld_c;
    const __nv_bfloat16* gbgh = s_wg[0] + bro;
    const __nv_bfloat16* gbgl = s_wg[1] + bro;
    const __nv_bfloat16* gbuh = s_wu[0] + bro;
    const __nv_bfloat16* gbul = s_wu[1] + bro;

    int wid = tid >> 5, lane = tid & 31;
    int wm0 = (wid >> 2) * 64, wn0 = (wid & 3) * 16;
    int a_loff = ((lane & 7) + ((lane >> 3) & 1) * 8) * AS2 + ((lane >> 4) & 1) * 8;
    int b_loff = ((lane & 7) + ((lane >> 4) & 1) * 8) * AS2 + ((lane >> 3) & 1) * 8;
    int g  = lane >> 2, tg = lane & 3;

    float accG[4][2][4], accU[4][2][4];
    #pragma unroll
    for (int i = 0; i < 4; i++)
        #pragma unroll
        for (int j = 0; j < 2; j++)
            #pragma unroll
            for (int k = 0; k < 4; k++) { accG[i][j][k] = 0.f; accU[i][j][k] = 0.f; }

    const int TS = D_DIM / 32;   // 32 stages
    int ld_dst = ld_row * AS2 + ld_c;

    auto load_stage = [&](int buf, int k0) {
        cp16b(&S.Ah[buf][ld_dst], gx0h + k0, ap0);
        cp16b(&S.Al[buf][ld_dst], gx0l + k0, ap0);
        cp16b(&S.Ah[buf][ld_dst + 64 * AS2], gx1h + k0, ap1);
        cp16b(&S.Al[buf][ld_dst + 64 * AS2], gx1l + k0, ap1);
        cp16b(&S.Bgh[buf][ld_dst], gbgh + k0, true);
        cp16b(&S.Bgl[buf][ld_dst], gbgl + k0, true);
        cp16b(&S.Buh[buf][ld_dst], gbuh + k0, true);
        cp16b(&S.Bul[buf][ld_dst], gbul + k0, true);
        cp_commit();
    };

    load_stage(0, 0);

    for (int t = 0; t < TS; t++) {
        if (t + 1 < TS) {
            load_stage((t + 1) & 1, (t + 1) * 32);
            cp_wait<1>();
        } else {
            cp_wait<0>();
        }
        __syncthreads();

        int buf = t & 1;
        const __nv_bfloat16* ah  = S.Ah[buf];
        const __nv_bfloat16* al  = S.Al[buf];
        const __nv_bfloat16* bgh = S.Bgh[buf];
        const __nv_bfloat16* bgl = S.Bgl[buf];
        const __nv_bfloat16* buh = S.Buh[buf];
        const __nv_bfloat16* bul = S.Bul[buf];

        #pragma unroll
        for (int sub = 0; sub < 2; sub++) {
            int ko = sub * 16;
            uint32_t afh[4][4], afl[4][4];
            #pragma unroll
            for (int mi = 0; mi < 4; mi++) {
                int ro = (wm0 + mi * 16) * AS2 + ko + a_loff;
                ldsm4(afh[mi][0], afh[mi][1], afh[mi][2], afh[mi][3], &ah[ro]);
                ldsm4(afl[mi][0], afl[mi][1], afl[mi][2], afl[mi][3], &al[ro]);
            }
            int bo = wn0 * AS2 + ko + b_loff;
            uint32_t gh[4], gl[4], uh[4], ul[4];
            ldsm4(gh[0], gh[1], gh[2], gh[3], &bgh[bo]);
            ldsm4(gl[0], gl[1], gl[2], gl[3], &bgl[bo]);
            ldsm4(uh[0], uh[1], uh[2], uh[3], &buh[bo]);
            ldsm4(ul[0], ul[1], ul[2], ul[3], &bul[bo]);
            #pragma unroll
            for (int ni = 0; ni < 2; ni++) {
                uint32_t bgh0 = gh[ni * 2], bgh1 = gh[ni * 2 + 1];
                uint32_t bgl0 = gl[ni * 2], bgl1 = gl[ni * 2 + 1];
                uint32_t buh0 = uh[ni * 2], buh1 = uh[ni * 2 + 1];
                uint32_t bul0 = ul[ni * 2], bul1 = ul[ni * 2 + 1];
                #pragma unroll
                for (int mi = 0; mi < 4; mi++) {
                    mma_bf16(accG[mi][ni], afh[mi][0], afh[mi][1], afh[mi][2], afh[mi][3], bgh0, bgh1);
                    mma_bf16(accG[mi][ni], afh[mi][0], afh[mi][1], afh[mi][2], afh[mi][3], bgl0, bgl1);
                    mma_bf16(accG[mi][ni], afl[mi][0], afl[mi][1], afl[mi][2], afl[mi][3], bgh0, bgh1);
                    mma_bf16(accU[mi][ni], afh[mi][0], afh[mi][1], afh[mi][2], afh[mi][3], buh0, buh1);
                    mma_bf16(accU[mi][ni], afh[mi][0], afh[mi][1], afh[mi][2], afh[mi][3], bul0, bul1);
                    mma_bf16(accU[mi][ni], afl[mi][0], afl[mi][1], afl[mi][2], afl[mi][3], buh0, buh1);
                }
            }
        }
        __syncthreads();
    }

    // epilogue: silu(g)*u -> split bf16 planes of H
    #pragma unroll
    for (int mi = 0; mi < 4; mi++) {
        #pragma unroll
        for (int ni = 0; ni < 2; ni++) {
            int col = n0 + wn0 + ni * 8 + tg * 2;
            #pragma unroll
            for (int half = 0; half < 2; half++) {
                int r = m0 + wm0 + mi * 16 + g + half * 8;
                if (r < cnt) {
                    size_t out = (size_t)(base + r) * I_DIM + col;
                    float gv0 = accG[mi][ni][half * 2];
                    float gv1 = accG[mi][ni][half * 2 + 1];
                    float h0 = gv0 / (1.f + expf(-gv0)) * accU[mi][ni][half * 2];
                    float h1 = gv1 / (1.f + expf(-gv1)) * accU[mi][ni][half * 2 + 1];
                    __nv_bfloat16 H0 = __float2bfloat16_rn(h0);
                    __nv_bfloat16 H1 = __float2bfloat16_rn(h1);
                    __nv_bfloat16 L0 = __float2bfloat16_rn(h0 - __bfloat162float(H0));
                    __nv_bfloat16 L1 = __float2bfloat16_rn(h1 - __bfloat162float(H1));
                    *(__nv_bfloat162*)&s_H[0][out] = __halves2bfloat162(H0, H1);
                    *(__nv_bfloat162*)&s_H[1][out] = __halves2bfloat162(L0, L1);
                }
            }
        }
    }
}

// =============================================================================
// gemm2: R5 structure, fused combine: atomicAdd prob*(H @ Wd^T) into y.
// Block 128(M) x 128(N), 256 threads, warp tile 64x32. 2 CTAs/SM forced.
// =============================================================================
struct Smem2 {
    __nv_bfloat16 Ah[2][128 * AS2], Al[2][128 * AS2];
    __nv_bfloat16 Bh[2][128 * AS2], Bl[2][128 * AS2];
    float rowprob[128];
    int   rowtok[128];
};

__global__ __launch_bounds__(256, 2) void gemm2_kernel(float* __restrict__ y) {
    extern __shared__ char smem_raw[];
    Smem2& S = *reinterpret_cast<Smem2*>(smem_raw);

    int e  = blockIdx.y >> 6;
    int mt = blockIdx.y & (MT_MAX - 1);
    int cnt = d_counts[e];
    int m0  = mt * 128;
    if (m0 >= cnt) return;
    int n0   = blockIdx.x * 128;
    int base = d_offsets[e];

    int tid = threadIdx.x;
    if (tid < 128) {
        int r = m0 + tid;
        bool v = r < cnt;
        S.rowprob[tid] = v ? d_pair_prob[base + r] : 0.f;
        S.rowtok[tid]  = v ? d_pair_token[base + r] : -1;
    }
    __syncthreads();

    int ld_row = tid >> 2;
    int ld_c   = (tid & 3) * 8;
    bool av0 = (m0 + ld_row) < cnt;
    bool av1 = (m0 + ld_row + 64) < cnt;
    size_t ar0 = (size_t)(base + (av0 ? m0 + ld_row : 0)) * I_DIM + ld_c;
    size_t ar1 = (size_t)(base + (av1 ? m0 + ld_row + 64 : 0)) * I_DIM + ld_c;
    const __nv_bfloat16* ga0h = s_H[0] + ar0;
    const __nv_bfloat16* ga0l = s_H[1] + ar0;
    const __nv_bfloat16* ga1h = s_H[0] + ar1;
    const __nv_bfloat16* ga1l = s_H[1] + ar1;

    size_t wE = (size_t)e * D_DIM * I_DIM;
    size_t br0 = wE + (size_t)(n0 + ld_row) * I_DIM + ld_c;
    size_t br1 = wE + (size_t)(n0 + ld_row + 64) * I_DIM + ld_c;
    const __nv_bfloat16* gb0h = s_wd[0] + br0;
    const __nv_bfloat16* gb0l = s_wd[1] + br0;
    const __nv_bfloat16* gb1h = s_wd[0] + br1;
    const __nv_bfloat16* gb1l = s_wd[1] + br1;

    int wid = tid >> 5, lane = tid & 31;
    int wm0 = (wid >> 2) * 64, wn0 = (wid & 3) * 32;
    int a_loff = ((lane & 7) + ((lane >> 3) & 1) * 8) * AS2 + ((lane >> 4) & 1) * 8;
    int b_loff = ((lane & 7) + ((lane >> 4) & 1) * 8) * AS2 + ((lane >> 3) & 1) * 8;
    int g  = lane >> 2, tg = lane & 3;

    float acc[4][4][4];
    #pragma unroll
    for (int i = 0; i < 4; i++)
        #pragma unroll
        for (int j = 0; j < 4; j++)
            #pragma unroll
            for (int k = 0; k < 4; k++) acc[i][j][k] = 0.f;

    const int TS = I_DIM / 32;   // 44 stages
    int ld_dst = ld_row * AS2 + ld_c;

    auto load_stage = [&](int buf, int k0) {
        cp16b(&S.Ah[buf][ld_dst], ga0h + k0, av0);
        cp16b(&S.Al[buf][ld_dst], ga0l + k0, av0);
        cp16b(&S.Ah[buf][ld_dst + 64 * AS2], ga1h + k0, av1);
        cp16b(&S.Al[buf][ld_dst + 64 * AS2], ga1l + k0, av1);
        cp16b(&S.Bh[buf][ld_dst], gb0h + k0, true);
        cp16b(&S.Bl[buf][ld_dst], gb0l + k0, true);
        cp16b(&S.Bh[buf][ld_dst + 64 * AS2], gb1h + k0, true);
        cp16b(&S.Bl[buf][ld_dst + 64 * AS2], gb1l + k0, true);
        cp_commit();
    };

    load_stage(0, 0);

    for (int t = 0; t < TS; t++) {
        if (t + 1 < TS) {
            load_stage((t + 1) & 1, (t + 1) * 32);
            cp_wait<1>();
        } else {
            cp_wait<0>();
        }
        __syncthreads();

        int buf = t & 1;
        const __nv_bfloat16* ah = S.Ah[buf];
        const __nv_bfloat16* al = S.Al[buf];
        const __nv_bfloat16* bh = S.Bh[buf];
        const __nv_bfloat16* bl = S.Bl[buf];

        #pragma unroll
        for (int sub = 0; sub < 2; sub++) {
            int ko = sub * 16;
            uint32_t afh[4][4], afl[4][4];
            #pragma unroll
            for (int mi = 0; mi < 4; mi++) {
                int ro = (wm0 + mi * 16) * AS2 + ko + a_loff;
                ldsm4(afh[mi][0], afh[mi][1], afh[mi][2], afh[mi][3], &ah[ro]);
                ldsm4(afl[mi][0], afl[mi][1], afl[mi][2], afl[mi][3], &al[ro]);
            }
            uint32_t bhr[2][4], blr[2][4];
            #pragma unroll
            for (int half = 0; half < 2; half++) {
                int bo = (wn0 + half * 16) * AS2 + ko + b_loff;
                ldsm4(bhr[half][0], bhr[half][1], bhr[half][2], bhr[half][3], &bh[bo]);
                ldsm4(blr[half][0], blr[half][1], blr[half][2], blr[half][3], &bl[bo]);
            }
            #pragma unroll
            for (int ni = 0; ni < 4; ni++) {
                uint32_t b0h = bhr[ni >> 1][(ni & 1) * 2], b1h = bhr[ni >> 1][(ni & 1) * 2 + 1];
                uint32_t b0l = blr[ni >> 1][(ni & 1) * 2], b1l = blr[ni >> 1][(ni & 1) * 2 + 1];
                #pragma unroll
                for (int mi = 0; mi < 4; mi++) {
                    mma_bf16(acc[mi][ni], afh[mi][0], afh[mi][1], afh[mi][2], afh[mi][3], b0h, b1h);
                    mma_bf16(acc[mi][ni], afh[mi][0], afh[mi][1], afh[mi][2], afh[mi][3], b0l, b1l);
                    mma_bf16(acc[mi][ni], afl[mi][0], afl[mi][1], afl[mi][2], afl[mi][3], b0h, b1h);
                }
            }
        }
        __syncthreads();
    }

    // epilogue: atomicAdd prob*acc directly into y[token]
    #pragma unroll
    for (int mi = 0; mi < 4; mi++) {
        #pragma unroll
        for (int half = 0; half < 2; half++) {
            int rb = wm0 + mi * 16 + g + half * 8;
            int r  = m0 + rb;
            if (r >= cnt) continue;
            float p  = S.rowprob[rb];
            int  tok = S.rowtok[rb];
            float* yp = y + (size_t)tok * D_DIM + n0 + wn0;
            #pragma unroll
            for (int ni = 0; ni < 4; ni++) {
                int col = ni * 8 + tg * 2;
                atomicAdd(&yp[col],     p * acc[mi][ni][half * 2]);
                atomicAdd(&yp[col + 1], p * acc[mi][ni][half * 2 + 1]);
            }
        }
    }
}

// ---------------- launch -----------------------------------------------------
extern "C" void kernel_launch(void* const* d_in, const int* in_sizes, int n_in,
                              void* d_out, int out_size) {
    const float* x  = (const float*)d_in[0];
    const float* gw = (const float*)d_in[1];
    const float* wg = (const float*)d_in[2];
    const float* wu = (const float*)d_in[3];
    const float* wd = (const float*)d_in[4];
    float* y = (float*)d_out;

    cudaFuncSetAttribute(gemm1_kernel, cudaFuncAttributeMaxDynamicSharedMemorySize, sizeof(Smem1));
    cudaFuncSetAttribute(gemm2_kernel, cudaFuncAttributeMaxDynamicSharedMemorySize, sizeof(Smem2));

    __nv_bfloat16 *p_x, *p_wg, *p_wu, *p_wd;
    cudaGetSymbolAddress((void**)&p_x,  s_x);
    cudaGetSymbolAddress((void**)&p_wg, s_wg);
    cudaGetSymbolAddress((void**)&p_wu, s_wu);
    cudaGetSymbolAddress((void**)&p_wd, s_wd);
    size_t xN = (size_t)N_TOK * D_DIM;

    init_kernel<<<1, 32>>>();
    zero_y_kernel<<<(N_TOK * D_DIM / 4 + 255) / 256, 256>>>((float4*)y, N_TOK * D_DIM / 4);
    router_kernel<<<N_TOK, 256>>>(x, gw);

    {   // splits
        int n4 = (int)(xN / 4);
        split_kernel<<<(n4 + 255) / 256, 256>>>((const float4*)x, (uint2*)p_x, (uint2*)(p_x + xN), n4);
        int w4 = (int)(W_ELEMS / 4);
        wsplit_kernel<<<dim3((w4 + 255) / 256, 3), 256>>>(
            (const float4*)wg, (const float4*)wu, (const float4*)wd,
            (uint2*)p_wg, (uint2*)(p_wg + W_ELEMS),
            (uint2*)p_wu, (uint2*)(p_wu + W_ELEMS),
            (uint2*)p_wd, (uint2*)(p_wd + W_ELEMS), w4);
    }

    scan_kernel<<<1, 1>>>();
    scatter_kernel<<<(N_TOK + 255) / 256, 256>>>();
    gemm1_kernel<<<dim3(I_DIM / 64, E_NUM * MT_MAX), 256, sizeof(Smem1)>>>();
    gemm2_kernel<<<dim3(D_DIM / 128, E_NUM * MT_MAX), 256, sizeof(Smem2)>>>(y);
}

// round 10
// speedup vs baseline: 1.6389x; 1.3453x over previous
#include <cuda_runtime.h>
#include <cuda_fp16.h>
#include <math.h>
#include <stdint.h>

#define N_TOK 4096
#define D_DIM 1024
#define E_NUM 8
#define I_DIM 1408
#define PAIRS (N_TOK * 2)
#define MT_MAX 64
#define AS2 40   // fp16 per smem row: 32 data + 8 pad (80B = 5x16B, ldsm conflict-free)

#define W_ELEMS ((size_t)E_NUM * I_DIM * D_DIM)

// ---------------- device scratch (static: allocation-guard safe) -------------
__device__ int   d_topk_idx[N_TOK * 2];
__device__ float d_topk_prob[N_TOK * 2];
__device__ int   d_counts[E_NUM];
__device__ int   d_offsets[E_NUM + 1];
__device__ int   d_cursor[E_NUM];
__device__ int   d_pair_token[PAIRS];
__device__ float d_pair_prob[PAIRS];

// x and H: fp16 hi/lo planes; weights: single fp16 plane
__device__ __half s_x [2][(size_t)N_TOK * D_DIM];
__device__ __half s_wg[W_ELEMS];
__device__ __half s_wu[W_ELEMS];
__device__ __half s_wd[W_ELEMS];
__device__ __half s_H [2][(size_t)PAIRS * I_DIM];

// ---------------- PTX helpers ------------------------------------------------
__device__ __forceinline__ void cp16h(__half* dst_smem, const __half* src, bool pred) {
    uint32_t d = (uint32_t)__cvta_generic_to_shared(dst_smem);
    int sz = pred ? 16 : 0;
    asm volatile("cp.async.cg.shared.global [%0], [%1], 16, %2;\n"
                 :: "r"(d), "l"(src), "r"(sz));
}
__device__ __forceinline__ void cp_commit() {
    asm volatile("cp.async.commit_group;\n");
}
template <int N>
__device__ __forceinline__ void cp_wait() {
    asm volatile("cp.async.wait_group %0;\n" :: "n"(N));
}
__device__ __forceinline__ void mma_f16(float c[4],
                                        uint32_t a0, uint32_t a1, uint32_t a2, uint32_t a3,
                                        uint32_t b0, uint32_t b1) {
    asm volatile(
        "mma.sync.aligned.m16n8k16.row.col.f32.f16.f16.f32 "
        "{%0,%1,%2,%3}, {%4,%5,%6,%7}, {%8,%9}, {%0,%1,%2,%3};\n"
        : "+f"(c[0]), "+f"(c[1]), "+f"(c[2]), "+f"(c[3])
        : "r"(a0), "r"(a1), "r"(a2), "r"(a3), "r"(b0), "r"(b1));
}
__device__ __forceinline__ void ldsm4(uint32_t& r0, uint32_t& r1, uint32_t& r2, uint32_t& r3,
                                      const __half* p) {
    uint32_t a = (uint32_t)__cvta_generic_to_shared(p);
    asm volatile("ldmatrix.sync.aligned.m8n8.x4.shared.b16 {%0,%1,%2,%3}, [%4];\n"
                 : "=r"(r0), "=r"(r1), "=r"(r2), "=r"(r3) : "r"(a));
}

// ---------------- split x: fp32 -> fp16 hi/lo planes -------------------------
__global__ void splitx_kernel(const float4* __restrict__ src,
                              uint2* __restrict__ hi, uint2* __restrict__ lo, int n4) {
    int i = blockIdx.x * blockDim.x + threadIdx.x;
    if (i >= n4) return;
    float4 v = src[i];
    __half h0 = __float2half_rn(v.x);
    __half h1 = __float2half_rn(v.y);
    __half h2 = __float2half_rn(v.z);
    __half h3 = __float2half_rn(v.w);
    __half l0 = __float2half_rn(v.x - __half2float(h0));
    __half l1 = __float2half_rn(v.y - __half2float(h1));
    __half l2 = __float2half_rn(v.z - __half2float(h2));
    __half l3 = __float2half_rn(v.w - __half2float(h3));
    __half2 hA = __halves2half2(h0, h1), hB = __halves2half2(h2, h3);
    __half2 lA = __halves2half2(l0, l1), lB = __halves2half2(l2, l3);
    uint2 ho, loo;
    ho.x  = *(uint32_t*)&hA;  ho.y  = *(uint32_t*)&hB;
    loo.x = *(uint32_t*)&lA;  loo.y = *(uint32_t*)&lB;
    hi[i] = ho;
    lo[i] = loo;
}

// round 3 weight matrices to single fp16 plane: blockIdx.y selects matrix
__global__ void wround_kernel(const float4* __restrict__ wg,
                              const float4* __restrict__ wu,
                              const float4* __restrict__ wd,
                              uint2* __restrict__ og,
                              uint2* __restrict__ ou,
                              uint2* __restrict__ od,
                              int n4) {
    int i = blockIdx.x * blockDim.x + threadIdx.x;
    if (i >= n4) return;
    const float4* src;
    uint2* dst;
    if (blockIdx.y == 0)      { src = wg; dst = og; }
    else if (blockIdx.y == 1) { src = wu; dst = ou; }
    else                      { src = wd; dst = od; }
    float4 v = src[i];
    __half2 hA = __halves2half2(__float2half_rn(v.x), __float2half_rn(v.y));
    __half2 hB = __halves2half2(__float2half_rn(v.z), __float2half_rn(v.w));
    uint2 o;
    o.x = *(uint32_t*)&hA;  o.y = *(uint32_t*)&hB;
    dst[i] = o;
}

// ---------------- init / zero / router / scan / scatter ----------------------
__global__ void init_kernel() {
    if (threadIdx.x < E_NUM) d_counts[threadIdx.x] = 0;
}

__global__ void zero_y_kernel(float4* __restrict__ y, int n4) {
    int i = blockIdx.x * blockDim.x + threadIdx.x;
    if (i < n4) y[i] = make_float4(0.f, 0.f, 0.f, 0.f);
}

__global__ void router_kernel(const float* __restrict__ x,
                              const float* __restrict__ gw) {
    __shared__ float xs[D_DIM];
    __shared__ float sc[E_NUM];
    int t = blockIdx.x;
    const float* xp = x + (size_t)t * D_DIM;
    for (int i = threadIdx.x; i < D_DIM; i += blockDim.x) xs[i] = xp[i];
    __syncthreads();
    int w = threadIdx.x >> 5, lane = threadIdx.x & 31;
    float s = 0.f;
    const float* g = gw + (size_t)w * D_DIM;
    for (int j = lane; j < D_DIM; j += 32) s += xs[j] * g[j];
    #pragma unroll
    for (int o = 16; o; o >>= 1) s += __shfl_xor_sync(0xffffffffu, s, o);
    if (lane == 0) sc[w] = s;
    __syncthreads();
    if (threadIdx.x == 0) {
        int i0 = 0; float s0 = sc[0];
        #pragma unroll
        for (int e = 1; e < E_NUM; e++) if (sc[e] > s0) { s0 = sc[e]; i0 = e; }
        int i1 = -1; float s1 = -1e30f;
        #pragma unroll
        for (int e = 0; e < E_NUM; e++)
            if (e != i0 && sc[e] > s1) { s1 = sc[e]; i1 = e; }
        float z  = expf(s1 - s0);
        float p0 = 1.f / (1.f + z);
        float p1 = z * p0;
        d_topk_idx[t * 2]     = i0;  d_topk_idx[t * 2 + 1]  = i1;
        d_topk_prob[t * 2]    = p0;  d_topk_prob[t * 2 + 1] = p1;
        atomicAdd(&d_counts[i0], 1);
        atomicAdd(&d_counts[i1], 1);
    }
}

__global__ void scan_kernel() {
    int off = 0;
    #pragma unroll
    for (int e = 0; e < E_NUM; e++) {
        d_offsets[e] = off;
        d_cursor[e]  = off;
        off += d_counts[e];
    }
    d_offsets[E_NUM] = off;
}

__global__ void scatter_kernel() {
    int t = blockIdx.x * blockDim.x + threadIdx.x;
    if (t >= N_TOK) return;
    #pragma unroll
    for (int k = 0; k < 2; k++) {
        int e = d_topk_idx[t * 2 + k];
        int pos = atomicAdd(&d_cursor[e], 1);
        d_pair_token[pos] = t;
        d_pair_prob[pos]  = d_topk_prob[t * 2 + k];
    }
}

// =============================================================================
// gemm1: H = silu(Xg @ Wg^T) * (Xg @ Wu^T) — fp16 2-term (Ah+Al)·Bh
// Block 128(M) x 64(N), 256 threads, warp tile 64x16, 2 CTAs/SM.
// =============================================================================
struct Smem1 {
    __half Ah[2][128 * AS2], Al[2][128 * AS2];
    __half Bg[2][64 * AS2],  Bu[2][64 * AS2];
    int rowtok[128];
};

__global__ __launch_bounds__(256, 2) void gemm1_kernel() {
    extern __shared__ char smem_raw[];
    Smem1& S = *reinterpret_cast<Smem1*>(smem_raw);

    int e  = blockIdx.y >> 6;
    int mt = blockIdx.y & (MT_MAX - 1);
    int cnt = d_counts[e];
    int m0  = mt * 128;
    if (m0 >= cnt) return;
    int n0   = blockIdx.x * 64;
    int base = d_offsets[e];

    int tid = threadIdx.x;
    if (tid < 128) {
        int r = m0 + tid;
        S.rowtok[tid] = (r < cnt) ? d_pair_token[base + r] : -1;
    }
    __syncthreads();

    int ld_row = tid >> 2;           // 0..63
    int ld_c   = (tid & 3) * 8;
    int tokA0 = S.rowtok[ld_row];
    int tokA1 = S.rowtok[ld_row + 64];
    const __half* gx0h = s_x[0] + (size_t)(tokA0 < 0 ? 0 : tokA0) * D_DIM + ld_c;
    const __half* gx0l = s_x[1] + (size_t)(tokA0 < 0 ? 0 : tokA0) * D_DIM + ld_c;
    const __half* gx1h = s_x[0] + (size_t)(tokA1 < 0 ? 0 : tokA1) * D_DIM + ld_c;
    const __half* gx1l = s_x[1] + (size_t)(tokA1 < 0 ? 0 : tokA1) * D_DIM + ld_c;
    bool ap0 = tokA0 >= 0, ap1 = tokA1 >= 0;

    size_t wE = (size_t)e * I_DIM * D_DIM;
    size_t bro = wE + (size_t)(n0 + ld_row) * D_DIM + ld_c;
    const __half* gbg = s_wg + bro;
    const __half* gbu = s_wu + bro;

    int wid = tid >> 5, lane = tid & 31;
    int wm0 = (wid >> 2) * 64, wn0 = (wid & 3) * 16;
    int a_loff = ((lane & 7) + ((lane >> 3) & 1) * 8) * AS2 + ((lane >> 4) & 1) * 8;
    int b_loff = ((lane & 7) + ((lane >> 4) & 1) * 8) * AS2 + ((lane >> 3) & 1) * 8;
    int g  = lane >> 2, tg = lane & 3;

    float accG[4][2][4], accU[4][2][4];
    #pragma unroll
    for (int i = 0; i < 4; i++)
        #pragma unroll
        for (int j = 0; j < 2; j++)
            #pragma unroll
            for (int k = 0; k < 4; k++) { accG[i][j][k] = 0.f; accU[i][j][k] = 0.f; }

    const int TS = D_DIM / 32;   // 32 stages
    int ld_dst = ld_row * AS2 + ld_c;

    auto load_stage = [&](int buf, int k0) {
        cp16h(&S.Ah[buf][ld_dst], gx0h + k0, ap0);
        cp16h(&S.Al[buf][ld_dst], gx0l + k0, ap0);
        cp16h(&S.Ah[buf][ld_dst + 64 * AS2], gx1h + k0, ap1);
        cp16h(&S.Al[buf][ld_dst + 64 * AS2], gx1l + k0, ap1);
        cp16h(&S.Bg[buf][ld_dst], gbg + k0, true);
        cp16h(&S.Bu[buf][ld_dst], gbu + k0, true);
        cp_commit();
    };

    load_stage(0, 0);

    for (int t = 0; t < TS; t++) {
        if (t + 1 < TS) {
            load_stage((t + 1) & 1, (t + 1) * 32);
            cp_wait<1>();
        } else {
            cp_wait<0>();
        }
        __syncthreads();

        int buf = t & 1;
        const __half* ah = S.Ah[buf];
        const __half* al = S.Al[buf];
        const __half* bg = S.Bg[buf];
        const __half* bu = S.Bu[buf];

        #pragma unroll
        for (int sub = 0; sub < 2; sub++) {
            int ko = sub * 16;
            uint32_t afh[4][4], afl[4][4];
            #pragma unroll
            for (int mi = 0; mi < 4; mi++) {
                int ro = (wm0 + mi * 16) * AS2 + ko + a_loff;
                ldsm4(afh[mi][0], afh[mi][1], afh[mi][2], afh[mi][3], &ah[ro]);
                ldsm4(afl[mi][0], afl[mi][1], afl[mi][2], afl[mi][3], &al[ro]);
            }
            int bo = wn0 * AS2 + ko + b_loff;
            uint32_t gh[4], uh[4];
            ldsm4(gh[0], gh[1], gh[2], gh[3], &bg[bo]);
            ldsm4(uh[0], uh[1], uh[2], uh[3], &bu[bo]);
            #pragma unroll
            for (int ni = 0; ni < 2; ni++) {
                uint32_t bg0 = gh[ni * 2], bg1 = gh[ni * 2 + 1];
                uint32_t bu0 = uh[ni * 2], bu1 = uh[ni * 2 + 1];
                #pragma unroll
                for (int mi = 0; mi < 4; mi++) {
                    mma_f16(accG[mi][ni], afh[mi][0], afh[mi][1], afh[mi][2], afh[mi][3], bg0, bg1);
                    mma_f16(accG[mi][ni], afl[mi][0], afl[mi][1], afl[mi][2], afl[mi][3], bg0, bg1);
                    mma_f16(accU[mi][ni], afh[mi][0], afh[mi][1], afh[mi][2], afh[mi][3], bu0, bu1);
                    mma_f16(accU[mi][ni], afl[mi][0], afl[mi][1], afl[mi][2], afl[mi][3], bu0, bu1);
                }
            }
        }
        __syncthreads();
    }

    // epilogue: silu(g)*u -> fp16 hi/lo planes of H
    #pragma unroll
    for (int mi = 0; mi < 4; mi++) {
        #pragma unroll
        for (int ni = 0; ni < 2; ni++) {
            int col = n0 + wn0 + ni * 8 + tg * 2;
            #pragma unroll
            for (int half = 0; half < 2; half++) {
                int r = m0 + wm0 + mi * 16 + g + half * 8;
                if (r < cnt) {
                    size_t out = (size_t)(base + r) * I_DIM + col;
                    float gv0 = accG[mi][ni][half * 2];
                    float gv1 = accG[mi][ni][half * 2 + 1];
                    float h0 = gv0 / (1.f + expf(-gv0)) * accU[mi][ni][half * 2];
                    float h1 = gv1 / (1.f + expf(-gv1)) * accU[mi][ni][half * 2 + 1];
                    __half H0 = __float2half_rn(h0);
                    __half H1 = __float2half_rn(h1);
                    __half L0 = __float2half_rn(h0 - __half2float(H0));
                    __half L1 = __float2half_rn(h1 - __half2float(H1));
                    *(__half2*)&s_H[0][out] = __halves2half2(H0, H1);
                    *(__half2*)&s_H[1][out] = __halves2half2(L0, L1);
                }
            }
        }
    }
}

// =============================================================================
// gemm2: y += prob * ((Hh+Hl) @ Wd^T), fp16 2-term, fused atomic combine.
// Block 128(M) x 128(N), 256 threads, warp tile 64x32, 2 CTAs/SM.
// =============================================================================
struct Smem2 {
    __half Ah[2][128 * AS2], Al[2][128 * AS2];
    __half Bh[2][128 * AS2];
    float rowprob[128];
    int   rowtok[128];
};

__global__ __launch_bounds__(256, 2) void gemm2_kernel(float* __restrict__ y) {
    extern __shared__ char smem_raw[];
    Smem2& S = *reinterpret_cast<Smem2*>(smem_raw);

    int e  = blockIdx.y >> 6;
    int mt = blockIdx.y & (MT_MAX - 1);
    int cnt = d_counts[e];
    int m0  = mt * 128;
    if (m0 >= cnt) return;
    int n0   = blockIdx.x * 128;
    int base = d_offsets[e];

    int tid = threadIdx.x;
    if (tid < 128) {
        int r = m0 + tid;
        bool v = r < cnt;
        S.rowprob[tid] = v ? d_pair_prob[base + r] : 0.f;
        S.rowtok[tid]  = v ? d_pair_token[base + r] : -1;
    }
    __syncthreads();

    int ld_row = tid >> 2;
    int ld_c   = (tid & 3) * 8;
    bool av0 = (m0 + ld_row) < cnt;
    bool av1 = (m0 + ld_row + 64) < cnt;
    size_t ar0 = (size_t)(base + (av0 ? m0 + ld_row : 0)) * I_DIM + ld_c;
    size_t ar1 = (size_t)(base + (av1 ? m0 + ld_row + 64 : 0)) * I_DIM + ld_c;
    const __half* ga0h = s_H[0] + ar0;
    const __half* ga0l = s_H[1] + ar0;
    const __half* ga1h = s_H[0] + ar1;
    const __half* ga1l = s_H[1] + ar1;

    size_t wE = (size_t)e * D_DIM * I_DIM;
    size_t br0 = wE + (size_t)(n0 + ld_row) * I_DIM + ld_c;
    size_t br1 = wE + (size_t)(n0 + ld_row + 64) * I_DIM + ld_c;
    const __half* gb0 = s_wd + br0;
    const __half* gb1 = s_wd + br1;

    int wid = tid >> 5, lane = tid & 31;
    int wm0 = (wid >> 2) * 64, wn0 = (wid & 3) * 32;
    int a_loff = ((lane & 7) + ((lane >> 3) & 1) * 8) * AS2 + ((lane >> 4) & 1) * 8;
    int b_loff = ((lane & 7) + ((lane >> 4) & 1) * 8) * AS2 + ((lane >> 3) & 1) * 8;
    int g  = lane >> 2, tg = lane & 3;

    float acc[4][4][4];
    #pragma unroll
    for (int i = 0; i < 4; i++)
        #pragma unroll
        for (int j = 0; j < 4; j++)
            #pragma unroll
            for (int k = 0; k < 4; k++) acc[i][j][k] = 0.f;

    const int TS = I_DIM / 32;   // 44 stages
    int ld_dst = ld_row * AS2 + ld_c;

    auto load_stage = [&](int buf, int k0) {
        cp16h(&S.Ah[buf][ld_dst], ga0h + k0, av0);
        cp16h(&S.Al[buf][ld_dst], ga0l + k0, av0);
        cp16h(&S.Ah[buf][ld_dst + 64 * AS2], ga1h + k0, av1);
        cp16h(&S.Al[buf][ld_dst + 64 * AS2], ga1l + k0, av1);
        cp16h(&S.Bh[buf][ld_dst], gb0 + k0, true);
        cp16h(&S.Bh[buf][ld_dst + 64 * AS2], gb1 + k0, true);
        cp_commit();
    };

    load_stage(0, 0);

    for (int t = 0; t < TS; t++) {
        if (t + 1 < TS) {
            load_stage((t + 1) & 1, (t + 1) * 32);
            cp_wait<1>();
        } else {
            cp_wait<0>();
        }
        __syncthreads();

        int buf = t & 1;
        const __half* ah = S.Ah[buf];
        const __half* al = S.Al[buf];
        const __half* bh = S.Bh[buf];

        #pragma unroll
        for (int sub = 0; sub < 2; sub++) {
            int ko = sub * 16;
            uint32_t afh[4][4], afl[4][4];
            #pragma unroll
            for (int mi = 0; mi < 4; mi++) {
                int ro = (wm0 + mi * 16) * AS2 + ko + a_loff;
                ldsm4(afh[mi][0], afh[mi][1], afh[mi][2], afh[mi][3], &ah[ro]);
                ldsm4(afl[mi][0], afl[mi][1], afl[mi][2], afl[mi][3], &al[ro]);
            }
            uint32_t bhr[2][4];
            #pragma unroll
            for (int half = 0; half < 2; half++) {
                int bo = (wn0 + half * 16) * AS2 + ko + b_loff;
                ldsm4(bhr[half][0], bhr[half][1], bhr[half][2], bhr[half][3], &bh[bo]);
            }
            #pragma unroll
            for (int ni = 0; ni < 4; ni++) {
                uint32_t b0 = bhr[ni >> 1][(ni & 1) * 2], b1 = bhr[ni >> 1][(ni & 1) * 2 + 1];
                #pragma unroll
                for (int mi = 0; mi < 4; mi++) {
                    mma_f16(acc[mi][ni], afh[mi][0], afh[mi][1], afh[mi][2], afh[mi][3], b0, b1);
                    mma_f16(acc[mi][ni], afl[mi][0], afl[mi][1], afl[mi][2], afl[mi][3], b0, b1);
                }
            }
        }
        __syncthreads();
    }

    // epilogue: atomicAdd prob*acc directly into y[token]
    #pragma unroll
    for (int mi = 0; mi < 4; mi++) {
        #pragma unroll
        for (int half = 0; half < 2; half++) {
            int rb = wm0 + mi * 16 + g + half * 8;
            int r  = m0 + rb;
            if (r >= cnt) continue;
            float p  = S.rowprob[rb];
            int  tok = S.rowtok[rb];
            float* yp = y + (size_t)tok * D_DIM + n0 + wn0;
            #pragma unroll
            for (int ni = 0; ni < 4; ni++) {
                int col = ni * 8 + tg * 2;
                atomicAdd(&yp[col],     p * acc[mi][ni][half * 2]);
                atomicAdd(&yp[col + 1], p * acc[mi][ni][half * 2 + 1]);
            }
        }
    }
}

// ---------------- launch -----------------------------------------------------
extern "C" void kernel_launch(void* const* d_in, const int* in_sizes, int n_in,
                              void* d_out, int out_size) {
    const float* x  = (const float*)d_in[0];
    const float* gw = (const float*)d_in[1];
    const float* wg = (const float*)d_in[2];
    const float* wu = (const float*)d_in[3];
    const float* wd = (const float*)d_in[4];
    float* y = (float*)d_out;

    cudaFuncSetAttribute(gemm1_kernel, cudaFuncAttributeMaxDynamicSharedMemorySize, sizeof(Smem1));
    cudaFuncSetAttribute(gemm2_kernel, cudaFuncAttributeMaxDynamicSharedMemorySize, sizeof(Smem2));

    __half *p_x, *p_wg, *p_wu, *p_wd;
    cudaGetSymbolAddress((void**)&p_x,  s_x);
    cudaGetSymbolAddress((void**)&p_wg, s_wg);
    cudaGetSymbolAddress((void**)&p_wu, s_wu);
    cudaGetSymbolAddress((void**)&p_wd, s_wd);
    size_t xN = (size_t)N_TOK * D_DIM;

    init_kernel<<<1, 32>>>();
    zero_y_kernel<<<(N_TOK * D_DIM / 4 + 255) / 256, 256>>>((float4*)y, N_TOK * D_DIM / 4);
    router_kernel<<<N_TOK, 256>>>(x, gw);

    {   // splits
        int n4 = (int)(xN / 4);
        splitx_kernel<<<(n4 + 255) / 256, 256>>>((const float4*)x, (uint2*)p_x, (uint2*)(p_x + xN), n4);
        int w4 = (int)(W_ELEMS / 4);
        wround_kernel<<<dim3((w4 + 255) / 256, 3), 256>>>(
            (const float4*)wg, (const float4*)wu, (const float4*)wd,
            (uint2*)p_wg, (uint2*)p_wu, (uint2*)p_wd, w4);
    }

    scan_kernel<<<1, 1>>>();
    scatter_kernel<<<(N_TOK + 255) / 256, 256>>>();
    gemm1_kernel<<<dim3(I_DIM / 64, E_NUM * MT_MAX), 256, sizeof(Smem1)>>>();
    gemm2_kernel<<<dim3(D_DIM / 128, E_NUM * MT_MAX), 256, sizeof(Smem2)>>>(y);
}

// round 11
// speedup vs baseline: 2.5172x; 1.5359x over previous
#include <cuda_runtime.h>
#include <cuda_fp16.h>
#include <math.h>
#include <stdint.h>

#define N_TOK 4096
#define D_DIM 1024
#define E_NUM 8
#define I_DIM 1408
#define PAIRS (N_TOK * 2)
#define MT_MAX 64
#define AS2 40   // fp16 per smem row: 32 data + 8 pad (80B = 5x16B, ldsm conflict-free)

#define W_ELEMS ((size_t)E_NUM * I_DIM * D_DIM)

// ---------------- device scratch (static: allocation-guard safe) -------------
__device__ int   d_topk_idx[N_TOK * 2];
__device__ float d_topk_prob[N_TOK * 2];
__device__ int   d_counts[E_NUM];
__device__ int   d_offsets[E_NUM + 1];
__device__ int   d_cursor[E_NUM];
__device__ int   d_pair_token[PAIRS];
__device__ float d_pair_prob[PAIRS];

// single fp16 planes everywhere
__device__ __half s_x [(size_t)N_TOK * D_DIM];
__device__ __half s_wg[W_ELEMS];
__device__ __half s_wu[W_ELEMS];
__device__ __half s_wd[W_ELEMS];
__device__ __half s_H [(size_t)PAIRS * I_DIM];

// ---------------- PTX helpers ------------------------------------------------
__device__ __forceinline__ void cp16h(__half* dst_smem, const __half* src, bool pred) {
    uint32_t d = (uint32_t)__cvta_generic_to_shared(dst_smem);
    int sz = pred ? 16 : 0;
    asm volatile("cp.async.cg.shared.global [%0], [%1], 16, %2;\n"
                 :: "r"(d), "l"(src), "r"(sz));
}
__device__ __forceinline__ void cp_commit() {
    asm volatile("cp.async.commit_group;\n");
}
template <int N>
__device__ __forceinline__ void cp_wait() {
    asm volatile("cp.async.wait_group %0;\n" :: "n"(N));
}
__device__ __forceinline__ void mma_f16(float c[4],
                                        uint32_t a0, uint32_t a1, uint32_t a2, uint32_t a3,
                                        uint32_t b0, uint32_t b1) {
    asm volatile(
        "mma.sync.aligned.m16n8k16.row.col.f32.f16.f16.f32 "
        "{%0,%1,%2,%3}, {%4,%5,%6,%7}, {%8,%9}, {%0,%1,%2,%3};\n"
        : "+f"(c[0]), "+f"(c[1]), "+f"(c[2]), "+f"(c[3])
        : "r"(a0), "r"(a1), "r"(a2), "r"(a3), "r"(b0), "r"(b1));
}
__device__ __forceinline__ void ldsm4(uint32_t& r0, uint32_t& r1, uint32_t& r2, uint32_t& r3,
                                      const __half* p) {
    uint32_t a = (uint32_t)__cvta_generic_to_shared(p);
    asm volatile("ldmatrix.sync.aligned.m8n8.x4.shared.b16 {%0,%1,%2,%3}, [%4];\n"
                 : "=r"(r0), "=r"(r1), "=r"(r2), "=r"(r3) : "r"(a));
}

// ---------------- round x: fp32 -> fp16 plane --------------------------------
__global__ void xround_kernel(const float4* __restrict__ src,
                              uint2* __restrict__ dst, int n4) {
    int i = blockIdx.x * blockDim.x + threadIdx.x;
    if (i >= n4) return;
    float4 v = src[i];
    __half2 hA = __halves2half2(__float2half_rn(v.x), __float2half_rn(v.y));
    __half2 hB = __halves2half2(__float2half_rn(v.z), __float2half_rn(v.w));
    uint2 o;
    o.x = *(uint32_t*)&hA;  o.y = *(uint32_t*)&hB;
    dst[i] = o;
}

// round 3 weight matrices: blockIdx.y selects matrix
__global__ void wround_kernel(const float4* __restrict__ wg,
                              const float4* __restrict__ wu,
                              const float4* __restrict__ wd,
                              uint2* __restrict__ og,
                              uint2* __restrict__ ou,
                              uint2* __restrict__ od,
                              int n4) {
    int i = blockIdx.x * blockDim.x + threadIdx.x;
    if (i >= n4) return;
    const float4* src;
    uint2* dst;
    if (blockIdx.y == 0)      { src = wg; dst = og; }
    else if (blockIdx.y == 1) { src = wu; dst = ou; }
    else                      { src = wd; dst = od; }
    float4 v = src[i];
    __half2 hA = __halves2half2(__float2half_rn(v.x), __float2half_rn(v.y));
    __half2 hB = __halves2half2(__float2half_rn(v.z), __float2half_rn(v.w));
    uint2 o;
    o.x = *(uint32_t*)&hA;  o.y = *(uint32_t*)&hB;
    dst[i] = o;
}

// ---------------- init / zero / router / scan / scatter ----------------------
__global__ void init_kernel() {
    if (threadIdx.x < E_NUM) d_counts[threadIdx.x] = 0;
}

__global__ void zero_y_kernel(float4* __restrict__ y, int n4) {
    int i = blockIdx.x * blockDim.x + threadIdx.x;
    if (i < n4) y[i] = make_float4(0.f, 0.f, 0.f, 0.f);
}

__global__ void router_kernel(const float* __restrict__ x,
                              const float* __restrict__ gw) {
    __shared__ float xs[D_DIM];
    __shared__ float sc[E_NUM];
    int t = blockIdx.x;
    const float* xp = x + (size_t)t * D_DIM;
    for (int i = threadIdx.x; i < D_DIM; i += blockDim.x) xs[i] = xp[i];
    __syncthreads();
    int w = threadIdx.x >> 5, lane = threadIdx.x & 31;
    float s = 0.f;
    const float* g = gw + (size_t)w * D_DIM;
    for (int j = lane; j < D_DIM; j += 32) s += xs[j] * g[j];
    #pragma unroll
    for (int o = 16; o; o >>= 1) s += __shfl_xor_sync(0xffffffffu, s, o);
    if (lane == 0) sc[w] = s;
    __syncthreads();
    if (threadIdx.x == 0) {
        int i0 = 0; float s0 = sc[0];
        #pragma unroll
        for (int e = 1; e < E_NUM; e++) if (sc[e] > s0) { s0 = sc[e]; i0 = e; }
        int i1 = -1; float s1 = -1e30f;
        #pragma unroll
        for (int e = 0; e < E_NUM; e++)
            if (e != i0 && sc[e] > s1) { s1 = sc[e]; i1 = e; }
        float z  = expf(s1 - s0);
        float p0 = 1.f / (1.f + z);
        float p1 = z * p0;
        d_topk_idx[t * 2]     = i0;  d_topk_idx[t * 2 + 1]  = i1;
        d_topk_prob[t * 2]    = p0;  d_topk_prob[t * 2 + 1] = p1;
        atomicAdd(&d_counts[i0], 1);
        atomicAdd(&d_counts[i1], 1);
    }
}

__global__ void scan_kernel() {
    int off = 0;
    #pragma unroll
    for (int e = 0; e < E_NUM; e++) {
        d_offsets[e] = off;
        d_cursor[e]  = off;
        off += d_counts[e];
    }
    d_offsets[E_NUM] = off;
}

__global__ void scatter_kernel() {
    int t = blockIdx.x * blockDim.x + threadIdx.x;
    if (t >= N_TOK) return;
    #pragma unroll
    for (int k = 0; k < 2; k++) {
        int e = d_topk_idx[t * 2 + k];
        int pos = atomicAdd(&d_cursor[e], 1);
        d_pair_token[pos] = t;
        d_pair_prob[pos]  = d_topk_prob[t * 2 + k];
    }
}

// =============================================================================
// gemm1: H = silu(X @ Wg^T) * (X @ Wu^T) — pure fp16, 1 MMA per product.
// Block 128(M) x 64(N), 256 threads, warp tile 64x16, 2 CTAs/SM.
// =============================================================================
struct Smem1 {
    __half A[2][128 * AS2];
    __half Bg[2][64 * AS2], Bu[2][64 * AS2];
    int rowtok[128];
};

__global__ __launch_bounds__(256, 2) void gemm1_kernel() {
    extern __shared__ char smem_raw[];
    Smem1& S = *reinterpret_cast<Smem1*>(smem_raw);

    int e  = blockIdx.y >> 6;
    int mt = blockIdx.y & (MT_MAX - 1);
    int cnt = d_counts[e];
    int m0  = mt * 128;
    if (m0 >= cnt) return;
    int n0   = blockIdx.x * 64;
    int base = d_offsets[e];

    int tid = threadIdx.x;
    if (tid < 128) {
        int r = m0 + tid;
        S.rowtok[tid] = (r < cnt) ? d_pair_token[base + r] : -1;
    }
    __syncthreads();

    int ld_row = tid >> 2;           // 0..63
    int ld_c   = (tid & 3) * 8;
    int tokA0 = S.rowtok[ld_row];
    int tokA1 = S.rowtok[ld_row + 64];
    const __half* gx0 = s_x + (size_t)(tokA0 < 0 ? 0 : tokA0) * D_DIM + ld_c;
    const __half* gx1 = s_x + (size_t)(tokA1 < 0 ? 0 : tokA1) * D_DIM + ld_c;
    bool ap0 = tokA0 >= 0, ap1 = tokA1 >= 0;

    size_t wE = (size_t)e * I_DIM * D_DIM;
    size_t bro = wE + (size_t)(n0 + ld_row) * D_DIM + ld_c;
    const __half* gbg = s_wg + bro;
    const __half* gbu = s_wu + bro;

    int wid = tid >> 5, lane = tid & 31;
    int wm0 = (wid >> 2) * 64, wn0 = (wid & 3) * 16;
    int a_loff = ((lane & 7) + ((lane >> 3) & 1) * 8) * AS2 + ((lane >> 4) & 1) * 8;
    int b_loff = ((lane & 7) + ((lane >> 4) & 1) * 8) * AS2 + ((lane >> 3) & 1) * 8;
    int g  = lane >> 2, tg = lane & 3;

    float accG[4][2][4], accU[4][2][4];
    #pragma unroll
    for (int i = 0; i < 4; i++)
        #pragma unroll
        for (int j = 0; j < 2; j++)
            #pragma unroll
            for (int k = 0; k < 4; k++) { accG[i][j][k] = 0.f; accU[i][j][k] = 0.f; }

    const int TS = D_DIM / 32;   // 32 stages
    int ld_dst = ld_row * AS2 + ld_c;

    auto load_stage = [&](int buf, int k0) {
        cp16h(&S.A[buf][ld_dst], gx0 + k0, ap0);
        cp16h(&S.A[buf][ld_dst + 64 * AS2], gx1 + k0, ap1);
        cp16h(&S.Bg[buf][ld_dst], gbg + k0, true);
        cp16h(&S.Bu[buf][ld_dst], gbu + k0, true);
        cp_commit();
    };

    load_stage(0, 0);

    for (int t = 0; t < TS; t++) {
        if (t + 1 < TS) {
            load_stage((t + 1) & 1, (t + 1) * 32);
            cp_wait<1>();
        } else {
            cp_wait<0>();
        }
        __syncthreads();

        int buf = t & 1;
        const __half* a  = S.A[buf];
        const __half* bg = S.Bg[buf];
        const __half* bu = S.Bu[buf];

        #pragma unroll
        for (int sub = 0; sub < 2; sub++) {
            int ko = sub * 16;
            uint32_t af[4][4];
            #pragma unroll
            for (int mi = 0; mi < 4; mi++) {
                int ro = (wm0 + mi * 16) * AS2 + ko + a_loff;
                ldsm4(af[mi][0], af[mi][1], af[mi][2], af[mi][3], &a[ro]);
            }
            int bo = wn0 * AS2 + ko + b_loff;
            uint32_t gh[4], uh[4];
            ldsm4(gh[0], gh[1], gh[2], gh[3], &bg[bo]);
            ldsm4(uh[0], uh[1], uh[2], uh[3], &bu[bo]);
            #pragma unroll
            for (int ni = 0; ni < 2; ni++) {
                uint32_t bg0 = gh[ni * 2], bg1 = gh[ni * 2 + 1];
                uint32_t bu0 = uh[ni * 2], bu1 = uh[ni * 2 + 1];
                #pragma unroll
                for (int mi = 0; mi < 4; mi++) {
                    mma_f16(accG[mi][ni], af[mi][0], af[mi][1], af[mi][2], af[mi][3], bg0, bg1);
                    mma_f16(accU[mi][ni], af[mi][0], af[mi][1], af[mi][2], af[mi][3], bu0, bu1);
                }
            }
        }
        __syncthreads();
    }

    // epilogue: silu(g)*u -> fp16 H
    #pragma unroll
    for (int mi = 0; mi < 4; mi++) {
        #pragma unroll
        for (int ni = 0; ni < 2; ni++) {
            int col = n0 + wn0 + ni * 8 + tg * 2;
            #pragma unroll
            for (int half = 0; half < 2; half++) {
                int r = m0 + wm0 + mi * 16 + g + half * 8;
                if (r < cnt) {
                    size_t out = (size_t)(base + r) * I_DIM + col;
                    float gv0 = accG[mi][ni][half * 2];
                    float gv1 = accG[mi][ni][half * 2 + 1];
                    float h0 = gv0 / (1.f + expf(-gv0)) * accU[mi][ni][half * 2];
                    float h1 = gv1 / (1.f + expf(-gv1)) * accU[mi][ni][half * 2 + 1];
                    *(__half2*)&s_H[out] = __halves2half2(__float2half_rn(h0), __float2half_rn(h1));
                }
            }
        }
    }
}

// =============================================================================
// gemm2: y += prob * (H @ Wd^T), pure fp16, fused atomic combine.
// Block 128(M) x 128(N), 256 threads, warp tile 64x32, 2 CTAs/SM.
// =============================================================================
struct Smem2 {
    __half A[2][128 * AS2];
    __half B[2][128 * AS2];
    float rowprob[128];
    int   rowtok[128];
};

__global__ __launch_bounds__(256, 2) void gemm2_kernel(float* __restrict__ y) {
    extern __shared__ char smem_raw[];
    Smem2& S = *reinterpret_cast<Smem2*>(smem_raw);

    int e  = blockIdx.y >> 6;
    int mt = blockIdx.y & (MT_MAX - 1);
    int cnt = d_counts[e];
    int m0  = mt * 128;
    if (m0 >= cnt) return;
    int n0   = blockIdx.x * 128;
    int base = d_offsets[e];

    int tid = threadIdx.x;
    if (tid < 128) {
        int r = m0 + tid;
        bool v = r < cnt;
        S.rowprob[tid] = v ? d_pair_prob[base + r] : 0.f;
        S.rowtok[tid]  = v ? d_pair_token[base + r] : -1;
    }
    __syncthreads();

    int ld_row = tid >> 2;
    int ld_c   = (tid & 3) * 8;
    bool av0 = (m0 + ld_row) < cnt;
    bool av1 = (m0 + ld_row + 64) < cnt;
    const __half* ga0 = s_H + (size_t)(base + (av0 ? m0 + ld_row : 0)) * I_DIM + ld_c;
    const __half* ga1 = s_H + (size_t)(base + (av1 ? m0 + ld_row + 64 : 0)) * I_DIM + ld_c;

    size_t wE = (size_t)e * D_DIM * I_DIM;
    const __half* gb0 = s_wd + wE + (size_t)(n0 + ld_row) * I_DIM + ld_c;
    const __half* gb1 = s_wd + wE + (size_t)(n0 + ld_row + 64) * I_DIM + ld_c;

    int wid = tid >> 5, lane = tid & 31;
    int wm0 = (wid >> 2) * 64, wn0 = (wid & 3) * 32;
    int a_loff = ((lane & 7) + ((lane >> 3) & 1) * 8) * AS2 + ((lane >> 4) & 1) * 8;
    int b_loff = ((lane & 7) + ((lane >> 4) & 1) * 8) * AS2 + ((lane >> 3) & 1) * 8;
    int g  = lane >> 2, tg = lane & 3;

    float acc[4][4][4];
    #pragma unroll
    for (int i = 0; i < 4; i++)
        #pragma unroll
        for (int j = 0; j < 4; j++)
            #pragma unroll
            for (int k = 0; k < 4; k++) acc[i][j][k] = 0.f;

    const int TS = I_DIM / 32;   // 44 stages
    int ld_dst = ld_row * AS2 + ld_c;

    auto load_stage = [&](int buf, int k0) {
        cp16h(&S.A[buf][ld_dst], ga0 + k0, av0);
        cp16h(&S.A[buf][ld_dst + 64 * AS2], ga1 + k0, av1);
        cp16h(&S.B[buf][ld_dst], gb0 + k0, true);
        cp16h(&S.B[buf][ld_dst + 64 * AS2], gb1 + k0, true);
        cp_commit();
    };

    load_stage(0, 0);

    for (int t = 0; t < TS; t++) {
        if (t + 1 < TS) {
            load_stage((t + 1) & 1, (t + 1) * 32);
            cp_wait<1>();
        } else {
            cp_wait<0>();
        }
        __syncthreads();

        int buf = t & 1;
        const __half* a = S.A[buf];
        const __half* b = S.B[buf];

        #pragma unroll
        for (int sub = 0; sub < 2; sub++) {
            int ko = sub * 16;
            uint32_t af[4][4];
            #pragma unroll
            for (int mi = 0; mi < 4; mi++) {
                int ro = (wm0 + mi * 16) * AS2 + ko + a_loff;
                ldsm4(af[mi][0], af[mi][1], af[mi][2], af[mi][3], &a[ro]);
            }
            uint32_t bhr[2][4];
            #pragma unroll
            for (int half = 0; half < 2; half++) {
                int bo = (wn0 + half * 16) * AS2 + ko + b_loff;
                ldsm4(bhr[half][0], bhr[half][1], bhr[half][2], bhr[half][3], &b[bo]);
            }
            #pragma unroll
            for (int ni = 0; ni < 4; ni++) {
                uint32_t b0 = bhr[ni >> 1][(ni & 1) * 2], b1 = bhr[ni >> 1][(ni & 1) * 2 + 1];
                #pragma unroll
                for (int mi = 0; mi < 4; mi++)
                    mma_f16(acc[mi][ni], af[mi][0], af[mi][1], af[mi][2], af[mi][3], b0, b1);
            }
        }
        __syncthreads();
    }

    // epilogue: atomicAdd prob*acc directly into y[token]
    #pragma unroll
    for (int mi = 0; mi < 4; mi++) {
        #pragma unroll
        for (int half = 0; half < 2; half++) {
            int rb = wm0 + mi * 16 + g + half * 8;
            int r  = m0 + rb;
            if (r >= cnt) continue;
            float p  = S.rowprob[rb];
            int  tok = S.rowtok[rb];
            float* yp = y + (size_t)tok * D_DIM + n0 + wn0;
            #pragma unroll
            for (int ni = 0; ni < 4; ni++) {
                int col = ni * 8 + tg * 2;
                atomicAdd(&yp[col],     p * acc[mi][ni][half * 2]);
                atomicAdd(&yp[col + 1], p * acc[mi][ni][half * 2 + 1]);
            }
        }
    }
}

// ---------------- launch -----------------------------------------------------
extern "C" void kernel_launch(void* const* d_in, const int* in_sizes, int n_in,
                              void* d_out, int out_size) {
    const float* x  = (const float*)d_in[0];
    const float* gw = (const float*)d_in[1];
    const float* wg = (const float*)d_in[2];
    const float* wu = (const float*)d_in[3];
    const float* wd = (const float*)d_in[4];
    float* y = (float*)d_out;

    cudaFuncSetAttribute(gemm1_kernel, cudaFuncAttributeMaxDynamicSharedMemorySize, sizeof(Smem1));
    cudaFuncSetAttribute(gemm2_kernel, cudaFuncAttributeMaxDynamicSharedMemorySize, sizeof(Smem2));

    __half *p_x, *p_wg, *p_wu, *p_wd;
    cudaGetSymbolAddress((void**)&p_x,  s_x);
    cudaGetSymbolAddress((void**)&p_wg, s_wg);
    cudaGetSymbolAddress((void**)&p_wu, s_wu);
    cudaGetSymbolAddress((void**)&p_wd, s_wd);
    size_t xN = (size_t)N_TOK * D_DIM;

    init_kernel<<<1, 32>>>();
    zero_y_kernel<<<(N_TOK * D_DIM / 4 + 255) / 256, 256>>>((float4*)y, N_TOK * D_DIM / 4);
    router_kernel<<<N_TOK, 256>>>(x, gw);

    {   // rounds
        int n4 = (int)(xN / 4);
        xround_kernel<<<(n4 + 255) / 256, 256>>>((const float4*)x, (uint2*)p_x, n4);
        int w4 = (int)(W_ELEMS / 4);
        wround_kernel<<<dim3((w4 + 255) / 256, 3), 256>>>(
            (const float4*)wg, (const float4*)wu, (const float4*)wd,
            (uint2*)p_wg, (uint2*)p_wu, (uint2*)p_wd, w4);
    }

    scan_kernel<<<1, 1>>>();
    scatter_kernel<<<(N_TOK + 255) / 256, 256>>>();
    gemm1_kernel<<<dim3(I_DIM / 64, E_NUM * MT_MAX), 256, sizeof(Smem1)>>>();
    gemm2_kernel<<<dim3(D_DIM / 128, E_NUM * MT_MAX), 256, sizeof(Smem2)>>>(y);
}